// round 11
// baseline (speedup 1.0000x reference)
#include <cuda_runtime.h>
#include <cstdint>

#define N_NODES 50000
#define N_EDGES 800000
#define D 256

#define BM 128
#define BN 128
#define BK 16
#define GEMM_MBLKS 391            // ceil(50000/128)

// ---------------- scratch (device globals; no allocations) ----------------
__device__ int   g_is64;
__device__ int   g_esrc[N_EDGES];
__device__ int   g_edst[N_EDGES];
__device__ int   g_deg[N_NODES];
__device__ int   g_rowptr[N_NODES + 1];
__device__ int   g_cursor[N_NODES];
__device__ int   g_srcs[N_EDGES];
__device__ int   g_eid[N_EDGES];
__device__ float g_bufA[N_NODES * D];   // agg scratch, later A_pre
__device__ float g_bufB[N_NODES * D];   // h1, later B_pre
__device__ float g_bufC[N_NODES * D];   // h2

__device__ __forceinline__ float* selbuf(int s) {
    if (s == 0) return g_bufA;
    if (s == 1) return g_bufB;
    if (s == 2) return g_bufC;
    return nullptr;
}

// ---------------- detect dtype + zero degrees (fused) ----------------
__global__ void detect_zero_kernel(const int* __restrict__ ei32) {
    int i = blockIdx.x * blockDim.x + threadIdx.x;
    if (i < N_NODES) g_deg[i] = 0;
    if (i == 0) {
        int allzero = 1;
        for (int j = 1; j < 256; j += 2) {
            if (ei32[j] != 0) { allzero = 0; break; }
        }
        g_is64 = allzero;
    }
}

// ---------------- convert edge index + count degrees (fused) ----------------
__global__ void convert_count_kernel(const void* __restrict__ ei) {
    int e = blockIdx.x * blockDim.x + threadIdx.x;
    if (e >= N_EDGES) return;
    int s, d;
    if (g_is64) {
        const long long* p = (const long long*)ei;
        s = (int)p[e];
        d = (int)p[N_EDGES + e];
    } else {
        const int* p = (const int*)ei;
        s = p[e];
        d = p[N_EDGES + e];
    }
    g_esrc[e] = s;
    g_edst[e] = d;
    atomicAdd(&g_deg[d], 1);
}

__global__ void scan_kernel() {
    __shared__ int sh[1024];
    const int CH = 49;
    int t = threadIdx.x;
    int base = t * CH;
    int s = 0;
    for (int i = 0; i < CH; i++) {
        int idx = base + i;
        if (idx < N_NODES) s += g_deg[idx];
    }
    sh[t] = s;
    __syncthreads();
    for (int o = 1; o < 1024; o <<= 1) {
        int v = (t >= o) ? sh[t - o] : 0;
        __syncthreads();
        sh[t] += v;
        __syncthreads();
    }
    int run = sh[t] - s;
    for (int i = 0; i < CH; i++) {
        int idx = base + i;
        if (idx < N_NODES) {
            g_rowptr[idx] = run;
            g_cursor[idx] = run;
            run += g_deg[idx];
        }
    }
    if (t == 0) g_rowptr[N_NODES] = N_EDGES;
}

__global__ void fill_kernel() {
    int e = blockIdx.x * blockDim.x + threadIdx.x;
    if (e < N_EDGES) {
        int pos = atomicAdd(&g_cursor[g_edst[e]], 1);
        g_srcs[pos] = g_esrc[e];
        g_eid[pos] = e;
    }
}

// ---------------- mean aggregation: one warp per node ----------------
__global__ void aggregate_kernel(const float* __restrict__ in_ext, int in_sel, int out_sel) {
    const float* in = in_ext ? in_ext : selbuf(in_sel);
    float* out = selbuf(out_sel);
    int gtid = blockIdx.x * blockDim.x + threadIdx.x;
    int node = gtid >> 5;
    int lane = gtid & 31;
    if (node >= N_NODES) return;
    int beg = g_rowptr[node], end = g_rowptr[node + 1];
    float4 acc0 = make_float4(0.f, 0.f, 0.f, 0.f);
    float4 acc1 = make_float4(0.f, 0.f, 0.f, 0.f);
    for (int p = beg; p < end; p++) {
        int s = g_srcs[p];
        const float4* ps = (const float4*)(in + (size_t)s * D);
        float4 a = ps[lane];
        float4 b = ps[lane + 32];
        acc0.x += a.x; acc0.y += a.y; acc0.z += a.z; acc0.w += a.w;
        acc1.x += b.x; acc1.y += b.y; acc1.z += b.z; acc1.w += b.w;
    }
    float inv = 1.f / fmaxf((float)(end - beg), 1.f);
    acc0.x *= inv; acc0.y *= inv; acc0.z *= inv; acc0.w *= inv;
    acc1.x *= inv; acc1.y *= inv; acc1.z *= inv; acc1.w *= inv;
    float4* po = (float4*)(out + (size_t)node * D);
    po[lane] = acc0;
    po[lane + 32] = acc1;
}

// ---------------- tf32 tensor-core GEMM ----------------
// C[M,256] = act(A1@W1 (+ A2@W2) (+ bias)), K = 256, row-major, stride 256.
// 128x128 block tile, BK=16 double-buffered, 8 warps of 32x64 (2x8 m16n8k8).
// A smem is k-PERMUTED (idx = (k&3)*4 + (k>>2)) so each thread's 4 A-frag
// values for both k-slices come from ONE LDS.128. B smem unchanged.
__device__ __forceinline__ uint32_t f2tf32(float f) {
    uint32_t r;
    asm("cvt.rna.tf32.f32 %0, %1;" : "=r"(r) : "f"(f));
    return r;
}

__device__ __forceinline__ uint4 cvt4(float4 v) {
    uint4 r;
    r.x = f2tf32(v.x); r.y = f2tf32(v.y); r.z = f2tf32(v.z); r.w = f2tf32(v.w);
    return r;
}

__device__ __forceinline__ void mma_tf32(float* c, uint32_t a0, uint32_t a1,
                                         uint32_t a2, uint32_t a3,
                                         uint32_t b0, uint32_t b1) {
    asm volatile(
        "mma.sync.aligned.m16n8k8.row.col.f32.tf32.tf32.f32 "
        "{%0,%1,%2,%3}, {%4,%5,%6,%7}, {%8,%9}, {%0,%1,%2,%3};"
        : "+f"(c[0]), "+f"(c[1]), "+f"(c[2]), "+f"(c[3])
        : "r"(a0), "r"(a1), "r"(a2), "r"(a3), "r"(b0), "r"(b1));
}

template <bool DUAL, bool RELU, bool BIAS>
__device__ __forceinline__ void gemm_body(
    const float* __restrict__ A1, const float* __restrict__ W1,
    const float* __restrict__ A2, const float* __restrict__ W2,
    const float* __restrict__ bias, float* __restrict__ C,
    int m0, int n0) {
    __shared__ uint32_t As[2][BM][20];        // k-permuted, stride 20
    __shared__ uint32_t Ws[2][BK][BN + 8];    // stride 136: conflict-free

    const int tid = threadIdx.x;
    const int lane = tid & 31;
    const int warp = tid >> 5;
    const int wm = warp & 3;
    const int wn = warp >> 2;

    const int itersPerPass = 256 / BK;           // 16
    const int total = DUAL ? 2 * itersPerPass : itersPerPass;

    float acc[2][8][4];
#pragma unroll
    for (int i = 0; i < 2; i++)
#pragma unroll
        for (int j = 0; j < 8; j++)
#pragma unroll
            for (int r = 0; r < 4; r++) acc[i][j][r] = 0.f;

    const int ar0 = tid >> 2, apc = tid & 3, ac0 = (tid & 3) * 4;
    const int ar1 = (tid + 256) >> 2;
    const int wk0 = tid >> 5, wc0 = (tid & 31) * 4;
    const int wk1 = (tid + 256) >> 5;

    auto loadA = [&](const float* A, int kk, float4& v0, float4& v1) {
        int gm0 = m0 + ar0, gm1 = m0 + ar1;
        v0 = (gm0 < N_NODES) ? *(const float4*)(A + (size_t)gm0 * 256 + kk + ac0)
                             : make_float4(0.f, 0.f, 0.f, 0.f);
        v1 = (gm1 < N_NODES) ? *(const float4*)(A + (size_t)gm1 * 256 + kk + ac0)
                             : make_float4(0.f, 0.f, 0.f, 0.f);
    };
    auto loadW = [&](const float* W, int kk, float4& v0, float4& v1) {
        v0 = *(const float4*)(W + (size_t)(kk + wk0) * 256 + n0 + wc0);
        v1 = *(const float4*)(W + (size_t)(kk + wk1) * 256 + n0 + wc0);
    };
    auto storeTile = [&](int buf, const float4& a0v, const float4& a1v,
                         const float4& w0v, const float4& w1v) {
        // A: float4 holds k = c..c+3 (c = apc*4); permuted index = j*4 + apc
        As[buf][ar0][apc]      = f2tf32(a0v.x);
        As[buf][ar0][4 + apc]  = f2tf32(a0v.y);
        As[buf][ar0][8 + apc]  = f2tf32(a0v.z);
        As[buf][ar0][12 + apc] = f2tf32(a0v.w);
        As[buf][ar1][apc]      = f2tf32(a1v.x);
        As[buf][ar1][4 + apc]  = f2tf32(a1v.y);
        As[buf][ar1][8 + apc]  = f2tf32(a1v.z);
        As[buf][ar1][12 + apc] = f2tf32(a1v.w);
        *(uint4*)&Ws[buf][wk0][wc0] = cvt4(w0v);
        *(uint4*)&Ws[buf][wk1][wc0] = cvt4(w1v);
    };

    {
        float4 a0v, a1v, w0v, w1v;
        loadA(A1, 0, a0v, a1v);
        loadW(W1, 0, w0v, w1v);
        storeTile(0, a0v, a1v, w0v, w1v);
    }
    __syncthreads();

    const int mbase = wm * 32;
    const int nbase = wn * 64;
    const int fr = lane >> 2;
    const int fc = lane & 3;

    for (int it = 0; it < total; it++) {
        int buf = it & 1;
        float4 pa0, pa1, pw0, pw1;
        bool more = (it + 1) < total;
        if (more) {
            int nit = it + 1;
            const float* A = (DUAL && nit >= itersPerPass) ? A2 : A1;
            const float* W = (DUAL && nit >= itersPerPass) ? W2 : W1;
            int kk = (nit & (itersPerPass - 1)) * BK;
            loadA(A, kk, pa0, pa1);
            loadW(W, kk, pw0, pw1);
        }

        // A fragments for BOTH k-slices: one LDS.128 per (mt,row)
        uint4 afr[2][2];
#pragma unroll
        for (int mt = 0; mt < 2; mt++) {
            int r = mbase + mt * 16 + fr;
            afr[mt][0] = *(const uint4*)&As[buf][r][fc * 4];      // k=fc,4+fc,8+fc,12+fc
            afr[mt][1] = *(const uint4*)&As[buf][r + 8][fc * 4];
        }

        // ks = 0 (k = fc, fc+4)
        {
            uint32_t bf[8][2];
#pragma unroll
            for (int nt = 0; nt < 8; nt++) {
                int n = nbase + nt * 8 + fr;
                bf[nt][0] = Ws[buf][fc][n];
                bf[nt][1] = Ws[buf][fc + 4][n];
            }
#pragma unroll
            for (int mt = 0; mt < 2; mt++)
#pragma unroll
                for (int nt = 0; nt < 8; nt++)
                    mma_tf32(acc[mt][nt], afr[mt][0].x, afr[mt][1].x,
                             afr[mt][0].y, afr[mt][1].y, bf[nt][0], bf[nt][1]);
        }
        // ks = 1 (k = 8+fc, 12+fc)
        {
            uint32_t bf[8][2];
#pragma unroll
            for (int nt = 0; nt < 8; nt++) {
                int n = nbase + nt * 8 + fr;
                bf[nt][0] = Ws[buf][8 + fc][n];
                bf[nt][1] = Ws[buf][12 + fc][n];
            }
#pragma unroll
            for (int mt = 0; mt < 2; mt++)
#pragma unroll
                for (int nt = 0; nt < 8; nt++)
                    mma_tf32(acc[mt][nt], afr[mt][0].z, afr[mt][1].z,
                             afr[mt][0].w, afr[mt][1].w, bf[nt][0], bf[nt][1]);
        }

        if (more) storeTile(buf ^ 1, pa0, pa1, pw0, pw1);
        __syncthreads();
    }

    // epilogue: c0/c1 at (fr, 2*fc), c2/c3 at (fr+8, 2*fc)
#pragma unroll
    for (int mt = 0; mt < 2; mt++) {
#pragma unroll
        for (int nt = 0; nt < 8; nt++) {
            int gn = n0 + nbase + nt * 8 + 2 * fc;
            float b0 = BIAS ? bias[gn] : 0.f;
            float b1 = BIAS ? bias[gn + 1] : 0.f;
            int gm0 = m0 + mbase + mt * 16 + fr;
            int gm1 = gm0 + 8;
            float2 v0, v1;
            v0.x = acc[mt][nt][0] + b0; v0.y = acc[mt][nt][1] + b1;
            v1.x = acc[mt][nt][2] + b0; v1.y = acc[mt][nt][3] + b1;
            if (RELU) {
                v0.x = fmaxf(v0.x, 0.f); v0.y = fmaxf(v0.y, 0.f);
                v1.x = fmaxf(v1.x, 0.f); v1.y = fmaxf(v1.y, 0.f);
            }
            if (gm0 < N_NODES) *(float2*)(C + (size_t)gm0 * 256 + gn) = v0;
            if (gm1 < N_NODES) *(float2*)(C + (size_t)gm1 * 256 + gn) = v1;
        }
    }
}

template <bool DUAL, bool RELU, bool BIAS>
__global__ __launch_bounds__(256, 2)
void gemm_kernel(const float* __restrict__ A1ext, int a1_sel,
                 const float* __restrict__ W1,
                 const float* __restrict__ A2ext, int a2_sel,
                 const float* __restrict__ W2,
                 const float* __restrict__ biasp, int c_sel) {
    const float* A1 = A1ext ? A1ext : selbuf(a1_sel);
    const float* A2 = DUAL ? (A2ext ? A2ext : selbuf(a2_sel)) : nullptr;
    gemm_body<DUAL, RELU, BIAS>(A1, W1, A2, W2, biasp, selbuf(c_sel),
                                blockIdx.y * BM, blockIdx.x * BN);
}

// merged edge precompute: blockIdx.x 0,1 -> bufA = h2@Wm1_top (no bias)
//                         blockIdx.x 2,3 -> bufB = h2@Wm1_bot + bm1
__global__ __launch_bounds__(256, 2)
void gemm_pre_kernel(const float* __restrict__ Wm1, const float* __restrict__ bm1) {
    int half = blockIdx.x >> 1;
    int n0 = (blockIdx.x & 1) * BN;
    const float* W = Wm1 + (size_t)half * 256 * 256;
    float* C = half ? g_bufB : g_bufA;
    if (half)
        gemm_body<false, false, true>(g_bufC, W, nullptr, nullptr, bm1, C,
                                      blockIdx.y * BM, n0);
    else
        gemm_body<false, false, false>(g_bufC, W, nullptr, nullptr, nullptr, C,
                                       blockIdx.y * BM, n0);
}

// ---------------- edge MLP, CSR order: one warp per DST node ----------------
__global__ void edge_kernel_csr(const float* __restrict__ Wm2,
                                const float* __restrict__ bm2,
                                float* __restrict__ out) {
    __shared__ __align__(16) float w0[256];
    __shared__ __align__(16) float w1[256];
    for (int i = threadIdx.x; i < 256; i += blockDim.x) {
        w0[i] = Wm2[i * 2 + 0];
        w1[i] = Wm2[i * 2 + 1];
    }
    __syncthreads();

    int gtid = blockIdx.x * blockDim.x + threadIdx.x;
    int node = gtid >> 5;
    int lane = gtid & 31;
    if (node >= N_NODES) return;

    int beg = g_rowptr[node], end = g_rowptr[node + 1];
    if (beg == end) return;

    const float4* pb = (const float4*)(g_bufB + (size_t)node * D);
    float4 b0 = pb[lane];
    float4 b1 = pb[lane + 32];

    const float4* w0f = (const float4*)w0;
    const float4* w1f = (const float4*)w1;
    float4 wa0 = w0f[lane], wa1 = w0f[lane + 32];
    float4 wb0 = w1f[lane], wb1 = w1f[lane + 32];

    float bias0 = bm2[0], bias1 = bm2[1];

    for (int p = beg; p < end; p++) {
        int s = g_srcs[p];
        int eid = g_eid[p];
        const float4* pa = (const float4*)(g_bufA + (size_t)s * D);
        float4 a0 = pa[lane];
        float4 a1 = pa[lane + 32];

        float4 v0, v1;
        v0.x = fmaxf(a0.x + b0.x, 0.f); v0.y = fmaxf(a0.y + b0.y, 0.f);
        v0.z = fmaxf(a0.z + b0.z, 0.f); v0.w = fmaxf(a0.w + b0.w, 0.f);
        v1.x = fmaxf(a1.x + b1.x, 0.f); v1.y = fmaxf(a1.y + b1.y, 0.f);
        v1.z = fmaxf(a1.z + b1.z, 0.f); v1.w = fmaxf(a1.w + b1.w, 0.f);

        float acc0 = 0.f, acc1 = 0.f;
        acc0 = fmaf(v0.x, wa0.x, acc0); acc0 = fmaf(v0.y, wa0.y, acc0);
        acc0 = fmaf(v0.z, wa0.z, acc0); acc0 = fmaf(v0.w, wa0.w, acc0);
        acc0 = fmaf(v1.x, wa1.x, acc0); acc0 = fmaf(v1.y, wa1.y, acc0);
        acc0 = fmaf(v1.z, wa1.z, acc0); acc0 = fmaf(v1.w, wa1.w, acc0);
        acc1 = fmaf(v0.x, wb0.x, acc1); acc1 = fmaf(v0.y, wb0.y, acc1);
        acc1 = fmaf(v0.z, wb0.z, acc1); acc1 = fmaf(v0.w, wb0.w, acc1);
        acc1 = fmaf(v1.x, wb1.x, acc1); acc1 = fmaf(v1.y, wb1.y, acc1);
        acc1 = fmaf(v1.z, wb1.z, acc1); acc1 = fmaf(v1.w, wb1.w, acc1);

#pragma unroll
        for (int o = 16; o > 0; o >>= 1) {
            acc0 += __shfl_xor_sync(0xFFFFFFFFu, acc0, o);
            acc1 += __shfl_xor_sync(0xFFFFFFFFu, acc1, o);
        }
        if (lane == 0) {
            float2 r;
            r.x = acc0 + bias0;
            r.y = acc1 + bias1;
            *(float2*)(out + (size_t)eid * 2) = r;
        }
    }
}

// ---------------- launch ----------------
extern "C" void kernel_launch(void* const* d_in, const int* in_sizes, int n_in,
                              void* d_out, int out_size) {
    const float* x   = (const float*)d_in[0];
    const void*  ei  = d_in[1];
    const float* W1l = (const float*)d_in[2];
    const float* b1l = (const float*)d_in[3];
    const float* W1r = (const float*)d_in[4];
    const float* W2l = (const float*)d_in[5];
    const float* b2l = (const float*)d_in[6];
    const float* W2r = (const float*)d_in[7];
    const float* Wm1 = (const float*)d_in[8];
    const float* bm1 = (const float*)d_in[9];
    const float* Wm2 = (const float*)d_in[10];
    const float* bm2 = (const float*)d_in[11];
    float* out = (float*)d_out;

    // detect dtype + zero degrees; convert + count (fused passes)
    detect_zero_kernel<<<(N_NODES + 255) / 256, 256>>>((const int*)ei);
    convert_count_kernel<<<(N_EDGES + 255) / 256, 256>>>(ei);
    scan_kernel<<<1, 1024>>>();
    fill_kernel<<<(N_EDGES + 255) / 256, 256>>>();

    dim3 ggrid(2, GEMM_MBLKS);
    dim3 pgrid(4, GEMM_MBLKS);
    int aggBlocks = (N_NODES * 32 + 255) / 256;

    // layer 1: agg(x) -> bufA ; h1 = relu(agg@W1l + x@W1r + b1l) -> bufB
    aggregate_kernel<<<aggBlocks, 256>>>(x, -1, 0);
    gemm_kernel<true, true, true><<<ggrid, 256>>>(nullptr, 0, W1l, x, -1, W1r, b1l, 1);

    // layer 2: agg(h1) -> bufA ; h2 = relu(agg@W2l + h1@W2r + b2l) -> bufC
    aggregate_kernel<<<aggBlocks, 256>>>(nullptr, 1, 0);
    gemm_kernel<true, true, true><<<ggrid, 256>>>(nullptr, 0, W2l, nullptr, 1, W2r, b2l, 2);

    // merged edge precompute: bufA = h2@Wm1_top ; bufB = h2@Wm1_bot + bm1
    gemm_pre_kernel<<<pgrid, 256>>>(Wm1, bm1);

    // edge MLP in CSR (dst-grouped) order
    edge_kernel_csr<<<aggBlocks, 256>>>(Wm2, bm2, out);
}

// round 12
// speedup vs baseline: 1.6180x; 1.6180x over previous
#include <cuda_runtime.h>
#include <cstdint>

#define N_NODES 50000
#define N_EDGES 800000
#define D 256

#define BM 128
#define BN 128
#define BK 16
#define GEMM_MBLKS 391            // ceil(50000/128)

// ---------------- scratch (device globals; no allocations) ----------------
__device__ int   g_is64;
__device__ int   g_esrc[N_EDGES];
__device__ int   g_edst[N_EDGES];
__device__ int   g_deg[N_NODES];
__device__ int   g_rowptr[N_NODES + 1];
__device__ int   g_cursor[N_NODES];
__device__ int2  g_edge[N_EDGES];       // (src, eid) packed, CSR order
__device__ float g_bufA[N_NODES * D];   // agg scratch, later A_pre
__device__ float g_bufB[N_NODES * D];   // h1, later B_pre
__device__ float g_bufC[N_NODES * D];   // h2

__device__ __forceinline__ float* selbuf(int s) {
    if (s == 0) return g_bufA;
    if (s == 1) return g_bufB;
    if (s == 2) return g_bufC;
    return nullptr;
}

// ---------------- detect dtype + zero degrees (fused) ----------------
__global__ void detect_zero_kernel(const int* __restrict__ ei32) {
    int i = blockIdx.x * blockDim.x + threadIdx.x;
    if (i < N_NODES) g_deg[i] = 0;
    if (i == 0) {
        int allzero = 1;
        for (int j = 1; j < 256; j += 2) {
            if (ei32[j] != 0) { allzero = 0; break; }
        }
        g_is64 = allzero;
    }
}

// ---------------- convert edge index + count degrees (fused) ----------------
__global__ void convert_count_kernel(const void* __restrict__ ei) {
    int e = blockIdx.x * blockDim.x + threadIdx.x;
    if (e >= N_EDGES) return;
    int s, d;
    if (g_is64) {
        const long long* p = (const long long*)ei;
        s = (int)p[e];
        d = (int)p[N_EDGES + e];
    } else {
        const int* p = (const int*)ei;
        s = p[e];
        d = p[N_EDGES + e];
    }
    g_esrc[e] = s;
    g_edst[e] = d;
    atomicAdd(&g_deg[d], 1);
}

__global__ void scan_kernel() {
    __shared__ int sh[1024];
    const int CH = 49;
    int t = threadIdx.x;
    int base = t * CH;
    int s = 0;
    for (int i = 0; i < CH; i++) {
        int idx = base + i;
        if (idx < N_NODES) s += g_deg[idx];
    }
    sh[t] = s;
    __syncthreads();
    for (int o = 1; o < 1024; o <<= 1) {
        int v = (t >= o) ? sh[t - o] : 0;
        __syncthreads();
        sh[t] += v;
        __syncthreads();
    }
    int run = sh[t] - s;
    for (int i = 0; i < CH; i++) {
        int idx = base + i;
        if (idx < N_NODES) {
            g_rowptr[idx] = run;
            g_cursor[idx] = run;
            run += g_deg[idx];
        }
    }
    if (t == 0) g_rowptr[N_NODES] = N_EDGES;
}

__global__ void fill_kernel() {
    int e = blockIdx.x * blockDim.x + threadIdx.x;
    if (e < N_EDGES) {
        int pos = atomicAdd(&g_cursor[g_edst[e]], 1);
        g_edge[pos] = make_int2(g_esrc[e], e);
    }
}

// ---------------- mean aggregation: one warp per node ----------------
__global__ void aggregate_kernel(const float* __restrict__ in_ext, int in_sel, int out_sel) {
    const float* in = in_ext ? in_ext : selbuf(in_sel);
    float* out = selbuf(out_sel);
    int gtid = blockIdx.x * blockDim.x + threadIdx.x;
    int node = gtid >> 5;
    int lane = gtid & 31;
    if (node >= N_NODES) return;
    int beg = g_rowptr[node], end = g_rowptr[node + 1];
    float4 acc0 = make_float4(0.f, 0.f, 0.f, 0.f);
    float4 acc1 = make_float4(0.f, 0.f, 0.f, 0.f);
    for (int p = beg; p < end; p++) {
        int s = g_edge[p].x;
        const float4* ps = (const float4*)(in + (size_t)s * D);
        float4 a = ps[lane];
        float4 b = ps[lane + 32];
        acc0.x += a.x; acc0.y += a.y; acc0.z += a.z; acc0.w += a.w;
        acc1.x += b.x; acc1.y += b.y; acc1.z += b.z; acc1.w += b.w;
    }
    float inv = 1.f / fmaxf((float)(end - beg), 1.f);
    acc0.x *= inv; acc0.y *= inv; acc0.z *= inv; acc0.w *= inv;
    acc1.x *= inv; acc1.y *= inv; acc1.z *= inv; acc1.w *= inv;
    float4* po = (float4*)(out + (size_t)node * D);
    po[lane] = acc0;
    po[lane + 32] = acc1;
}

// ---------------- tf32 tensor-core GEMM (R8-proven layout) ----------------
// C[M,256] = act(A1@W1 (+ A2@W2) (+ bias)), K = 256, row-major, stride 256.
// 128x128 block tile, BK=16 double-buffered, 8 warps of 32x64 (2x8 m16n8k8).
// Smem holds pre-converted tf32 bits; inner loop is pure scalar LDS + MMA.
__device__ __forceinline__ uint32_t f2tf32(float f) {
    uint32_t r;
    asm("cvt.rna.tf32.f32 %0, %1;" : "=r"(r) : "f"(f));
    return r;
}

__device__ __forceinline__ uint4 cvt4(float4 v) {
    uint4 r;
    r.x = f2tf32(v.x); r.y = f2tf32(v.y); r.z = f2tf32(v.z); r.w = f2tf32(v.w);
    return r;
}

__device__ __forceinline__ void mma_tf32(float* c, uint32_t a0, uint32_t a1,
                                         uint32_t a2, uint32_t a3,
                                         uint32_t b0, uint32_t b1) {
    asm volatile(
        "mma.sync.aligned.m16n8k8.row.col.f32.tf32.tf32.f32 "
        "{%0,%1,%2,%3}, {%4,%5,%6,%7}, {%8,%9}, {%0,%1,%2,%3};"
        : "+f"(c[0]), "+f"(c[1]), "+f"(c[2]), "+f"(c[3])
        : "r"(a0), "r"(a1), "r"(a2), "r"(a3), "r"(b0), "r"(b1));
}

template <bool DUAL, bool RELU, bool BIAS>
__device__ __forceinline__ void gemm_body(
    const float* __restrict__ A1, const float* __restrict__ W1,
    const float* __restrict__ A2, const float* __restrict__ W2,
    const float* __restrict__ bias, float* __restrict__ C,
    int m0, int n0) {
    __shared__ uint32_t As[2][BM][BK + 4];    // stride 20: conflict-free
    __shared__ uint32_t Ws[2][BK][BN + 8];    // stride 136: conflict-free

    const int tid = threadIdx.x;
    const int lane = tid & 31;
    const int warp = tid >> 5;
    const int wm = warp & 3;
    const int wn = warp >> 2;

    const int itersPerPass = 256 / BK;           // 16
    const int total = DUAL ? 2 * itersPerPass : itersPerPass;

    float acc[2][8][4];
#pragma unroll
    for (int i = 0; i < 2; i++)
#pragma unroll
        for (int j = 0; j < 8; j++)
#pragma unroll
            for (int r = 0; r < 4; r++) acc[i][j][r] = 0.f;

    const int ar0 = tid >> 2, ac0 = (tid & 3) * 4;
    const int ar1 = (tid + 256) >> 2;
    const int wk0 = tid >> 5, wc0 = (tid & 31) * 4;
    const int wk1 = (tid + 256) >> 5;

    auto loadA = [&](const float* A, int kk, float4& v0, float4& v1) {
        int gm0 = m0 + ar0, gm1 = m0 + ar1;
        v0 = (gm0 < N_NODES) ? *(const float4*)(A + (size_t)gm0 * 256 + kk + ac0)
                             : make_float4(0.f, 0.f, 0.f, 0.f);
        v1 = (gm1 < N_NODES) ? *(const float4*)(A + (size_t)gm1 * 256 + kk + ac0)
                             : make_float4(0.f, 0.f, 0.f, 0.f);
    };
    auto loadW = [&](const float* W, int kk, float4& v0, float4& v1) {
        v0 = *(const float4*)(W + (size_t)(kk + wk0) * 256 + n0 + wc0);
        v1 = *(const float4*)(W + (size_t)(kk + wk1) * 256 + n0 + wc0);
    };
    auto storeTile = [&](int buf, const float4& a0v, const float4& a1v,
                         const float4& w0v, const float4& w1v) {
        *(uint4*)&As[buf][ar0][ac0] = cvt4(a0v);
        *(uint4*)&As[buf][ar1][ac0] = cvt4(a1v);
        *(uint4*)&Ws[buf][wk0][wc0] = cvt4(w0v);
        *(uint4*)&Ws[buf][wk1][wc0] = cvt4(w1v);
    };

    {
        float4 a0v, a1v, w0v, w1v;
        loadA(A1, 0, a0v, a1v);
        loadW(W1, 0, w0v, w1v);
        storeTile(0, a0v, a1v, w0v, w1v);
    }
    __syncthreads();

    const int mbase = wm * 32;
    const int nbase = wn * 64;
    const int fr = lane >> 2;
    const int fc = lane & 3;

    for (int it = 0; it < total; it++) {
        int buf = it & 1;
        float4 pa0, pa1, pw0, pw1;
        bool more = (it + 1) < total;
        if (more) {
            int nit = it + 1;
            const float* A = (DUAL && nit >= itersPerPass) ? A2 : A1;
            const float* W = (DUAL && nit >= itersPerPass) ? W2 : W1;
            int kk = (nit & (itersPerPass - 1)) * BK;
            loadA(A, kk, pa0, pa1);
            loadW(W, kk, pw0, pw1);
        }

#pragma unroll
        for (int ks = 0; ks < 2; ks++) {
            int kk = ks * 8;
            uint32_t af[2][4];
#pragma unroll
            for (int mt = 0; mt < 2; mt++) {
                int r = mbase + mt * 16 + fr;
                af[mt][0] = As[buf][r][kk + fc];
                af[mt][1] = As[buf][r + 8][kk + fc];
                af[mt][2] = As[buf][r][kk + fc + 4];
                af[mt][3] = As[buf][r + 8][kk + fc + 4];
            }
            uint32_t bf[8][2];
#pragma unroll
            for (int nt = 0; nt < 8; nt++) {
                int n = nbase + nt * 8 + fr;
                bf[nt][0] = Ws[buf][kk + fc][n];
                bf[nt][1] = Ws[buf][kk + fc + 4][n];
            }
#pragma unroll
            for (int mt = 0; mt < 2; mt++)
#pragma unroll
                for (int nt = 0; nt < 8; nt++)
                    mma_tf32(acc[mt][nt], af[mt][0], af[mt][1], af[mt][2], af[mt][3],
                             bf[nt][0], bf[nt][1]);
        }

        if (more) storeTile(buf ^ 1, pa0, pa1, pw0, pw1);
        __syncthreads();
    }

    // epilogue
#pragma unroll
    for (int mt = 0; mt < 2; mt++) {
#pragma unroll
        for (int nt = 0; nt < 8; nt++) {
            int gn = n0 + nbase + nt * 8 + 2 * fc;
            float b0 = BIAS ? bias[gn] : 0.f;
            float b1 = BIAS ? bias[gn + 1] : 0.f;
            int gm0 = m0 + mbase + mt * 16 + fr;
            int gm1 = gm0 + 8;
            float2 v0, v1;
            v0.x = acc[mt][nt][0] + b0; v0.y = acc[mt][nt][1] + b1;
            v1.x = acc[mt][nt][2] + b0; v1.y = acc[mt][nt][3] + b1;
            if (RELU) {
                v0.x = fmaxf(v0.x, 0.f); v0.y = fmaxf(v0.y, 0.f);
                v1.x = fmaxf(v1.x, 0.f); v1.y = fmaxf(v1.y, 0.f);
            }
            if (gm0 < N_NODES) *(float2*)(C + (size_t)gm0 * 256 + gn) = v0;
            if (gm1 < N_NODES) *(float2*)(C + (size_t)gm1 * 256 + gn) = v1;
        }
    }
}

template <bool DUAL, bool RELU, bool BIAS>
__global__ __launch_bounds__(256, 2)
void gemm_kernel(const float* __restrict__ A1ext, int a1_sel,
                 const float* __restrict__ W1,
                 const float* __restrict__ A2ext, int a2_sel,
                 const float* __restrict__ W2,
                 const float* __restrict__ biasp, int c_sel) {
    const float* A1 = A1ext ? A1ext : selbuf(a1_sel);
    const float* A2 = DUAL ? (A2ext ? A2ext : selbuf(a2_sel)) : nullptr;
    gemm_body<DUAL, RELU, BIAS>(A1, W1, A2, W2, biasp, selbuf(c_sel),
                                blockIdx.y * BM, blockIdx.x * BN);
}

// merged edge precompute: blockIdx.x 0,1 -> bufA = h2@Wm1_top (no bias)
//                         blockIdx.x 2,3 -> bufB = h2@Wm1_bot + bm1
__global__ __launch_bounds__(256, 2)
void gemm_pre_kernel(const float* __restrict__ Wm1, const float* __restrict__ bm1) {
    int half = blockIdx.x >> 1;
    int n0 = (blockIdx.x & 1) * BN;
    const float* W = Wm1 + (size_t)half * 256 * 256;
    float* C = half ? g_bufB : g_bufA;
    if (half)
        gemm_body<false, false, true>(g_bufC, W, nullptr, nullptr, bm1, C,
                                      blockIdx.y * BM, n0);
    else
        gemm_body<false, false, false>(g_bufC, W, nullptr, nullptr, nullptr, C,
                                       blockIdx.y * BM, n0);
}

// ---------------- edge MLP, CSR order: one warp per DST node ----------------
__global__ void edge_kernel_csr(const float* __restrict__ Wm2,
                                const float* __restrict__ bm2,
                                float* __restrict__ out) {
    __shared__ __align__(16) float w0[256];
    __shared__ __align__(16) float w1[256];
    for (int i = threadIdx.x; i < 256; i += blockDim.x) {
        w0[i] = Wm2[i * 2 + 0];
        w1[i] = Wm2[i * 2 + 1];
    }
    __syncthreads();

    int gtid = blockIdx.x * blockDim.x + threadIdx.x;
    int node = gtid >> 5;
    int lane = gtid & 31;
    if (node >= N_NODES) return;

    int beg = g_rowptr[node], end = g_rowptr[node + 1];
    if (beg == end) return;

    const float4* pb = (const float4*)(g_bufB + (size_t)node * D);
    float4 b0 = pb[lane];
    float4 b1 = pb[lane + 32];

    const float4* w0f = (const float4*)w0;
    const float4* w1f = (const float4*)w1;
    float4 wa0 = w0f[lane], wa1 = w0f[lane + 32];
    float4 wb0 = w1f[lane], wb1 = w1f[lane + 32];

    float bias0 = bm2[0], bias1 = bm2[1];

    for (int p = beg; p < end; p++) {
        int2 se = g_edge[p];
        int s = se.x;
        int eid = se.y;
        const float4* pa = (const float4*)(g_bufA + (size_t)s * D);
        float4 a0 = pa[lane];
        float4 a1 = pa[lane + 32];

        float4 v0, v1;
        v0.x = fmaxf(a0.x + b0.x, 0.f); v0.y = fmaxf(a0.y + b0.y, 0.f);
        v0.z = fmaxf(a0.z + b0.z, 0.f); v0.w = fmaxf(a0.w + b0.w, 0.f);
        v1.x = fmaxf(a1.x + b1.x, 0.f); v1.y = fmaxf(a1.y + b1.y, 0.f);
        v1.z = fmaxf(a1.z + b1.z, 0.f); v1.w = fmaxf(a1.w + b1.w, 0.f);

        float acc0 = 0.f, acc1 = 0.f;
        acc0 = fmaf(v0.x, wa0.x, acc0); acc0 = fmaf(v0.y, wa0.y, acc0);
        acc0 = fmaf(v0.z, wa0.z, acc0); acc0 = fmaf(v0.w, wa0.w, acc0);
        acc0 = fmaf(v1.x, wa1.x, acc0); acc0 = fmaf(v1.y, wa1.y, acc0);
        acc0 = fmaf(v1.z, wa1.z, acc0); acc0 = fmaf(v1.w, wa1.w, acc0);
        acc1 = fmaf(v0.x, wb0.x, acc1); acc1 = fmaf(v0.y, wb0.y, acc1);
        acc1 = fmaf(v0.z, wb0.z, acc1); acc1 = fmaf(v0.w, wb0.w, acc1);
        acc1 = fmaf(v1.x, wb1.x, acc1); acc1 = fmaf(v1.y, wb1.y, acc1);
        acc1 = fmaf(v1.z, wb1.z, acc1); acc1 = fmaf(v1.w, wb1.w, acc1);

#pragma unroll
        for (int o = 16; o > 0; o >>= 1) {
            acc0 += __shfl_xor_sync(0xFFFFFFFFu, acc0, o);
            acc1 += __shfl_xor_sync(0xFFFFFFFFu, acc1, o);
        }
        if (lane == 0) {
            float2 r;
            r.x = acc0 + bias0;
            r.y = acc1 + bias1;
            *(float2*)(out + (size_t)eid * 2) = r;
        }
    }
}

// ---------------- launch ----------------
extern "C" void kernel_launch(void* const* d_in, const int* in_sizes, int n_in,
                              void* d_out, int out_size) {
    const float* x   = (const float*)d_in[0];
    const void*  ei  = d_in[1];
    const float* W1l = (const float*)d_in[2];
    const float* b1l = (const float*)d_in[3];
    const float* W1r = (const float*)d_in[4];
    const float* W2l = (const float*)d_in[5];
    const float* b2l = (const float*)d_in[6];
    const float* W2r = (const float*)d_in[7];
    const float* Wm1 = (const float*)d_in[8];
    const float* bm1 = (const float*)d_in[9];
    const float* Wm2 = (const float*)d_in[10];
    const float* bm2 = (const float*)d_in[11];
    float* out = (float*)d_out;

    // detect dtype + zero degrees; convert + count (fused passes)
    detect_zero_kernel<<<(N_NODES + 255) / 256, 256>>>((const int*)ei);
    convert_count_kernel<<<(N_EDGES + 255) / 256, 256>>>(ei);
    scan_kernel<<<1, 1024>>>();
    fill_kernel<<<(N_EDGES + 255) / 256, 256>>>();

    dim3 ggrid(2, GEMM_MBLKS);
    dim3 pgrid(4, GEMM_MBLKS);
    int aggBlocks = (N_NODES * 32 + 255) / 256;

    // layer 1: agg(x) -> bufA ; h1 = relu(agg@W1l + x@W1r + b1l) -> bufB
    aggregate_kernel<<<aggBlocks, 256>>>(x, -1, 0);
    gemm_kernel<true, true, true><<<ggrid, 256>>>(nullptr, 0, W1l, x, -1, W1r, b1l, 1);

    // layer 2: agg(h1) -> bufA ; h2 = relu(agg@W2l + h1@W2r + b2l) -> bufC
    aggregate_kernel<<<aggBlocks, 256>>>(nullptr, 1, 0);
    gemm_kernel<true, true, true><<<ggrid, 256>>>(nullptr, 0, W2l, nullptr, 1, W2r, b2l, 2);

    // merged edge precompute: bufA = h2@Wm1_top ; bufB = h2@Wm1_bot + bm1
    gemm_pre_kernel<<<pgrid, 256>>>(Wm1, bm1);

    // edge MLP in CSR (dst-grouped) order
    edge_kernel_csr<<<aggBlocks, 256>>>(Wm2, bm2, out);
}

// round 13
// speedup vs baseline: 1.9047x; 1.1772x over previous
#include <cuda_runtime.h>
#include <cuda_fp16.h>
#include <cstdint>

#define N_NODES 50000
#define N_EDGES 800000
#define D 256

#define BM 128
#define BN 128
#define BK 16
#define GEMM_MBLKS 391            // ceil(50000/128)

// ---------------- scratch (device globals; no allocations) ----------------
__device__ int   g_is64;
__device__ int   g_esrc[N_EDGES];
__device__ int   g_edst[N_EDGES];
__device__ int   g_deg[N_NODES];
__device__ int   g_rowptr[N_NODES + 1];
__device__ int   g_cursor[N_NODES];
__device__ int2  g_edge[N_EDGES];       // (src, eid) packed, CSR order
__device__ float g_bufA[N_NODES * D];   // agg scratch, later A_pre
__device__ float g_bufB[N_NODES * D];   // h1, later B_pre
__device__ float g_bufC[N_NODES * D];   // h2

__device__ __forceinline__ float* selbuf(int s) {
    if (s == 0) return g_bufA;
    if (s == 1) return g_bufB;
    if (s == 2) return g_bufC;
    return nullptr;
}

// ---------------- detect dtype + zero degrees (fused) ----------------
__global__ void detect_zero_kernel(const int* __restrict__ ei32) {
    int i = blockIdx.x * blockDim.x + threadIdx.x;
    if (i < N_NODES) g_deg[i] = 0;
    if (i == 0) {
        int allzero = 1;
        for (int j = 1; j < 256; j += 2) {
            if (ei32[j] != 0) { allzero = 0; break; }
        }
        g_is64 = allzero;
    }
}

// ---------------- convert edge index + count degrees (fused) ----------------
__global__ void convert_count_kernel(const void* __restrict__ ei) {
    int e = blockIdx.x * blockDim.x + threadIdx.x;
    if (e >= N_EDGES) return;
    int s, d;
    if (g_is64) {
        const long long* p = (const long long*)ei;
        s = (int)p[e];
        d = (int)p[N_EDGES + e];
    } else {
        const int* p = (const int*)ei;
        s = p[e];
        d = p[N_EDGES + e];
    }
    g_esrc[e] = s;
    g_edst[e] = d;
    atomicAdd(&g_deg[d], 1);
}

__global__ void scan_kernel() {
    __shared__ int sh[1024];
    const int CH = 49;
    int t = threadIdx.x;
    int base = t * CH;
    int s = 0;
    for (int i = 0; i < CH; i++) {
        int idx = base + i;
        if (idx < N_NODES) s += g_deg[idx];
    }
    sh[t] = s;
    __syncthreads();
    for (int o = 1; o < 1024; o <<= 1) {
        int v = (t >= o) ? sh[t - o] : 0;
        __syncthreads();
        sh[t] += v;
        __syncthreads();
    }
    int run = sh[t] - s;
    for (int i = 0; i < CH; i++) {
        int idx = base + i;
        if (idx < N_NODES) {
            g_rowptr[idx] = run;
            g_cursor[idx] = run;
            run += g_deg[idx];
        }
    }
    if (t == 0) g_rowptr[N_NODES] = N_EDGES;
}

__global__ void fill_kernel() {
    int e = blockIdx.x * blockDim.x + threadIdx.x;
    if (e < N_EDGES) {
        int pos = atomicAdd(&g_cursor[g_edst[e]], 1);
        g_edge[pos] = make_int2(g_esrc[e], e);
    }
}

// ---------------- mean aggregation: one warp per node ----------------
__global__ void aggregate_kernel(const float* __restrict__ in_ext, int in_sel, int out_sel) {
    const float* in = in_ext ? in_ext : selbuf(in_sel);
    float* out = selbuf(out_sel);
    int gtid = blockIdx.x * blockDim.x + threadIdx.x;
    int node = gtid >> 5;
    int lane = gtid & 31;
    if (node >= N_NODES) return;
    int beg = g_rowptr[node], end = g_rowptr[node + 1];
    float4 acc0 = make_float4(0.f, 0.f, 0.f, 0.f);
    float4 acc1 = make_float4(0.f, 0.f, 0.f, 0.f);
    for (int p = beg; p < end; p++) {
        int s = g_edge[p].x;
        const float4* ps = (const float4*)(in + (size_t)s * D);
        float4 a = ps[lane];
        float4 b = ps[lane + 32];
        acc0.x += a.x; acc0.y += a.y; acc0.z += a.z; acc0.w += a.w;
        acc1.x += b.x; acc1.y += b.y; acc1.z += b.z; acc1.w += b.w;
    }
    float inv = 1.f / fmaxf((float)(end - beg), 1.f);
    acc0.x *= inv; acc0.y *= inv; acc0.z *= inv; acc0.w *= inv;
    acc1.x *= inv; acc1.y *= inv; acc1.z *= inv; acc1.w *= inv;
    float4* po = (float4*)(out + (size_t)node * D);
    po[lane] = acc0;
    po[lane + 32] = acc1;
}

// ---------------- fp16 tensor-core GEMM ----------------
// C[M,256] = act(A1@W1 (+ A2@W2) (+ bias)), K = 256, row-major, stride 256.
// 128x128 block tile, BK=16 double-buffered, 8 warps of 32x64, m16n8k16 f16.
// Smem holds packed half2 (fp16 mantissa == tf32 mantissa; inputs are O(1)).
// As[r][k2] = (A[r][2k2], A[r][2k2+1]);  Ws[k2][n] = (W[2k2][n], W[2k2+1][n]).
__device__ __forceinline__ uint32_t packh2(float a, float b) {
    __half2 h = __floats2half2_rn(a, b);
    return *(uint32_t*)&h;
}

__device__ __forceinline__ void mma_f16(float* c, uint32_t a0, uint32_t a1,
                                        uint32_t a2, uint32_t a3,
                                        uint32_t b0, uint32_t b1) {
    asm volatile(
        "mma.sync.aligned.m16n8k16.row.col.f32.f16.f16.f32 "
        "{%0,%1,%2,%3}, {%4,%5,%6,%7}, {%8,%9}, {%0,%1,%2,%3};"
        : "+f"(c[0]), "+f"(c[1]), "+f"(c[2]), "+f"(c[3])
        : "r"(a0), "r"(a1), "r"(a2), "r"(a3), "r"(b0), "r"(b1));
}

template <bool DUAL, bool RELU, bool BIAS>
__device__ __forceinline__ void gemm_body(
    const float* __restrict__ A1, const float* __restrict__ W1,
    const float* __restrict__ A2, const float* __restrict__ W2,
    const float* __restrict__ bias, float* __restrict__ C,
    int m0, int n0) {
    __shared__ uint32_t As[2][BM][12];        // 8 half2 cols + 4 pad (stride 12)
    __shared__ uint32_t Ws[2][8][BN + 8];     // 8 k-pair rows, stride 136

    const int tid = threadIdx.x;
    const int lane = tid & 31;
    const int warp = tid >> 5;
    const int wm = warp & 3;
    const int wn = warp >> 2;

    const int itersPerPass = 256 / BK;           // 16
    const int total = DUAL ? 2 * itersPerPass : itersPerPass;

    float acc[2][8][4];
#pragma unroll
    for (int i = 0; i < 2; i++)
#pragma unroll
        for (int j = 0; j < 8; j++)
#pragma unroll
            for (int r = 0; r < 4; r++) acc[i][j][r] = 0.f;

    // A tile: 128 rows x 16 k; thread loads rows ar0, ar1 with float4 at k-offset ac0
    const int ar0 = tid >> 2, ac0 = (tid & 3) * 4, ah0 = (tid & 3) * 2;
    const int ar1 = (tid + 256) >> 2;
    // W tile: 16 k x 128 n; thread loads k rows 2*wi, 2*wi+1 at n-offset wn4
    const int wi = tid >> 5, wn4 = (tid & 31) * 4;

    auto loadA = [&](const float* A, int kk, float4& v0, float4& v1) {
        int gm0 = m0 + ar0, gm1 = m0 + ar1;
        v0 = (gm0 < N_NODES) ? *(const float4*)(A + (size_t)gm0 * 256 + kk + ac0)
                             : make_float4(0.f, 0.f, 0.f, 0.f);
        v1 = (gm1 < N_NODES) ? *(const float4*)(A + (size_t)gm1 * 256 + kk + ac0)
                             : make_float4(0.f, 0.f, 0.f, 0.f);
    };
    auto loadW = [&](const float* W, int kk, float4& v0, float4& v1) {
        v0 = *(const float4*)(W + (size_t)(kk + 2 * wi) * 256 + n0 + wn4);
        v1 = *(const float4*)(W + (size_t)(kk + 2 * wi + 1) * 256 + n0 + wn4);
    };
    auto storeTile = [&](int buf, const float4& a0v, const float4& a1v,
                         const float4& w0v, const float4& w1v) {
        // A: float4 covers k = ac0..ac0+3 -> half2 cols ah0, ah0+1
        *(uint2*)&As[buf][ar0][ah0] =
            make_uint2(packh2(a0v.x, a0v.y), packh2(a0v.z, a0v.w));
        *(uint2*)&As[buf][ar1][ah0] =
            make_uint2(packh2(a1v.x, a1v.y), packh2(a1v.z, a1v.w));
        // W: pair rows 2wi,2wi+1 -> Ws[wi][wn4..wn4+3]
        uint4 wp;
        wp.x = packh2(w0v.x, w1v.x);
        wp.y = packh2(w0v.y, w1v.y);
        wp.z = packh2(w0v.z, w1v.z);
        wp.w = packh2(w0v.w, w1v.w);
        *(uint4*)&Ws[buf][wi][wn4] = wp;
    };

    {
        float4 a0v, a1v, w0v, w1v;
        loadA(A1, 0, a0v, a1v);
        loadW(W1, 0, w0v, w1v);
        storeTile(0, a0v, a1v, w0v, w1v);
    }
    __syncthreads();

    const int mbase = wm * 32;
    const int nbase = wn * 64;
    const int fr = lane >> 2;
    const int fc = lane & 3;

    for (int it = 0; it < total; it++) {
        int buf = it & 1;
        float4 pa0, pa1, pw0, pw1;
        bool more = (it + 1) < total;
        if (more) {
            int nit = it + 1;
            const float* A = (DUAL && nit >= itersPerPass) ? A2 : A1;
            const float* W = (DUAL && nit >= itersPerPass) ? W2 : W1;
            int kk = (nit & (itersPerPass - 1)) * BK;
            loadA(A, kk, pa0, pa1);
            loadW(W, kk, pw0, pw1);
        }

        // fragments: one m16n8k16 per (mt, nt)
        uint32_t af[2][4];
#pragma unroll
        for (int mt = 0; mt < 2; mt++) {
            int r = mbase + mt * 16 + fr;
            af[mt][0] = As[buf][r][fc];          // k = 2fc, 2fc+1
            af[mt][1] = As[buf][r + 8][fc];
            af[mt][2] = As[buf][r][fc + 4];      // k = 8+2fc, 9+2fc
            af[mt][3] = As[buf][r + 8][fc + 4];
        }
        uint32_t bf[8][2];
#pragma unroll
        for (int nt = 0; nt < 8; nt++) {
            int n = nbase + nt * 8 + fr;
            bf[nt][0] = Ws[buf][fc][n];
            bf[nt][1] = Ws[buf][fc + 4][n];
        }
#pragma unroll
        for (int mt = 0; mt < 2; mt++)
#pragma unroll
            for (int nt = 0; nt < 8; nt++)
                mma_f16(acc[mt][nt], af[mt][0], af[mt][1], af[mt][2], af[mt][3],
                        bf[nt][0], bf[nt][1]);

        if (more) storeTile(buf ^ 1, pa0, pa1, pw0, pw1);
        __syncthreads();
    }

    // epilogue: c0/c1 at (fr, 2*fc), c2/c3 at (fr+8, 2*fc)
#pragma unroll
    for (int mt = 0; mt < 2; mt++) {
#pragma unroll
        for (int nt = 0; nt < 8; nt++) {
            int gn = n0 + nbase + nt * 8 + 2 * fc;
            float b0 = BIAS ? bias[gn] : 0.f;
            float b1 = BIAS ? bias[gn + 1] : 0.f;
            int gm0 = m0 + mbase + mt * 16 + fr;
            int gm1 = gm0 + 8;
            float2 v0, v1;
            v0.x = acc[mt][nt][0] + b0; v0.y = acc[mt][nt][1] + b1;
            v1.x = acc[mt][nt][2] + b0; v1.y = acc[mt][nt][3] + b1;
            if (RELU) {
                v0.x = fmaxf(v0.x, 0.f); v0.y = fmaxf(v0.y, 0.f);
                v1.x = fmaxf(v1.x, 0.f); v1.y = fmaxf(v1.y, 0.f);
            }
            if (gm0 < N_NODES) *(float2*)(C + (size_t)gm0 * 256 + gn) = v0;
            if (gm1 < N_NODES) *(float2*)(C + (size_t)gm1 * 256 + gn) = v1;
        }
    }
}

template <bool DUAL, bool RELU, bool BIAS>
__global__ __launch_bounds__(256, 2)
void gemm_kernel(const float* __restrict__ A1ext, int a1_sel,
                 const float* __restrict__ W1,
                 const float* __restrict__ A2ext, int a2_sel,
                 const float* __restrict__ W2,
                 const float* __restrict__ biasp, int c_sel) {
    const float* A1 = A1ext ? A1ext : selbuf(a1_sel);
    const float* A2 = DUAL ? (A2ext ? A2ext : selbuf(a2_sel)) : nullptr;
    gemm_body<DUAL, RELU, BIAS>(A1, W1, A2, W2, biasp, selbuf(c_sel),
                                blockIdx.y * BM, blockIdx.x * BN);
}

// merged edge precompute: blockIdx.x 0,1 -> bufA = h2@Wm1_top (no bias)
//                         blockIdx.x 2,3 -> bufB = h2@Wm1_bot + bm1
__global__ __launch_bounds__(256, 2)
void gemm_pre_kernel(const float* __restrict__ Wm1, const float* __restrict__ bm1) {
    int half = blockIdx.x >> 1;
    int n0 = (blockIdx.x & 1) * BN;
    const float* W = Wm1 + (size_t)half * 256 * 256;
    float* C = half ? g_bufB : g_bufA;
    if (half)
        gemm_body<false, false, true>(g_bufC, W, nullptr, nullptr, bm1, C,
                                      blockIdx.y * BM, n0);
    else
        gemm_body<false, false, false>(g_bufC, W, nullptr, nullptr, nullptr, C,
                                       blockIdx.y * BM, n0);
}

// ---------------- edge MLP, CSR order: one warp per DST node ----------------
__global__ void edge_kernel_csr(const float* __restrict__ Wm2,
                                const float* __restrict__ bm2,
                                float* __restrict__ out) {
    __shared__ __align__(16) float w0[256];
    __shared__ __align__(16) float w1[256];
    for (int i = threadIdx.x; i < 256; i += blockDim.x) {
        w0[i] = Wm2[i * 2 + 0];
        w1[i] = Wm2[i * 2 + 1];
    }
    __syncthreads();

    int gtid = blockIdx.x * blockDim.x + threadIdx.x;
    int node = gtid >> 5;
    int lane = gtid & 31;
    if (node >= N_NODES) return;

    int beg = g_rowptr[node], end = g_rowptr[node + 1];
    if (beg == end) return;

    const float4* pb = (const float4*)(g_bufB + (size_t)node * D);
    float4 b0 = pb[lane];
    float4 b1 = pb[lane + 32];

    const float4* w0f = (const float4*)w0;
    const float4* w1f = (const float4*)w1;
    float4 wa0 = w0f[lane], wa1 = w0f[lane + 32];
    float4 wb0 = w1f[lane], wb1 = w1f[lane + 32];

    float bias0 = bm2[0], bias1 = bm2[1];

    for (int p = beg; p < end; p++) {
        int2 se = g_edge[p];
        int s = se.x;
        int eid = se.y;
        const float4* pa = (const float4*)(g_bufA + (size_t)s * D);
        float4 a0 = pa[lane];
        float4 a1 = pa[lane + 32];

        float4 v0, v1;
        v0.x = fmaxf(a0.x + b0.x, 0.f); v0.y = fmaxf(a0.y + b0.y, 0.f);
        v0.z = fmaxf(a0.z + b0.z, 0.f); v0.w = fmaxf(a0.w + b0.w, 0.f);
        v1.x = fmaxf(a1.x + b1.x, 0.f); v1.y = fmaxf(a1.y + b1.y, 0.f);
        v1.z = fmaxf(a1.z + b1.z, 0.f); v1.w = fmaxf(a1.w + b1.w, 0.f);

        float acc0 = 0.f, acc1 = 0.f;
        acc0 = fmaf(v0.x, wa0.x, acc0); acc0 = fmaf(v0.y, wa0.y, acc0);
        acc0 = fmaf(v0.z, wa0.z, acc0); acc0 = fmaf(v0.w, wa0.w, acc0);
        acc0 = fmaf(v1.x, wa1.x, acc0); acc0 = fmaf(v1.y, wa1.y, acc0);
        acc0 = fmaf(v1.z, wa1.z, acc0); acc0 = fmaf(v1.w, wa1.w, acc0);
        acc1 = fmaf(v0.x, wb0.x, acc1); acc1 = fmaf(v0.y, wb0.y, acc1);
        acc1 = fmaf(v0.z, wb0.z, acc1); acc1 = fmaf(v0.w, wb0.w, acc1);
        acc1 = fmaf(v1.x, wb1.x, acc1); acc1 = fmaf(v1.y, wb1.y, acc1);
        acc1 = fmaf(v1.z, wb1.z, acc1); acc1 = fmaf(v1.w, wb1.w, acc1);

#pragma unroll
        for (int o = 16; o > 0; o >>= 1) {
            acc0 += __shfl_xor_sync(0xFFFFFFFFu, acc0, o);
            acc1 += __shfl_xor_sync(0xFFFFFFFFu, acc1, o);
        }
        if (lane == 0) {
            float2 r;
            r.x = acc0 + bias0;
            r.y = acc1 + bias1;
            *(float2*)(out + (size_t)eid * 2) = r;
        }
    }
}

// ---------------- launch ----------------
extern "C" void kernel_launch(void* const* d_in, const int* in_sizes, int n_in,
                              void* d_out, int out_size) {
    const float* x   = (const float*)d_in[0];
    const void*  ei  = d_in[1];
    const float* W1l = (const float*)d_in[2];
    const float* b1l = (const float*)d_in[3];
    const float* W1r = (const float*)d_in[4];
    const float* W2l = (const float*)d_in[5];
    const float* b2l = (const float*)d_in[6];
    const float* W2r = (const float*)d_in[7];
    const float* Wm1 = (const float*)d_in[8];
    const float* bm1 = (const float*)d_in[9];
    const float* Wm2 = (const float*)d_in[10];
    const float* bm2 = (const float*)d_in[11];
    float* out = (float*)d_out;

    // detect dtype + zero degrees; convert + count (fused passes)
    detect_zero_kernel<<<(N_NODES + 255) / 256, 256>>>((const int*)ei);
    convert_count_kernel<<<(N_EDGES + 255) / 256, 256>>>(ei);
    scan_kernel<<<1, 1024>>>();
    fill_kernel<<<(N_EDGES + 255) / 256, 256>>>();

    dim3 ggrid(2, GEMM_MBLKS);
    dim3 pgrid(4, GEMM_MBLKS);
    int aggBlocks = (N_NODES * 32 + 255) / 256;

    // layer 1: agg(x) -> bufA ; h1 = relu(agg@W1l + x@W1r + b1l) -> bufB
    aggregate_kernel<<<aggBlocks, 256>>>(x, -1, 0);
    gemm_kernel<true, true, true><<<ggrid, 256>>>(nullptr, 0, W1l, x, -1, W1r, b1l, 1);

    // layer 2: agg(h1) -> bufA ; h2 = relu(agg@W2l + h1@W2r + b2l) -> bufC
    aggregate_kernel<<<aggBlocks, 256>>>(nullptr, 1, 0);
    gemm_kernel<true, true, true><<<ggrid, 256>>>(nullptr, 0, W2l, nullptr, 1, W2r, b2l, 2);

    // merged edge precompute: bufA = h2@Wm1_top ; bufB = h2@Wm1_bot + bm1
    gemm_pre_kernel<<<pgrid, 256>>>(Wm1, bm1);

    // edge MLP in CSR (dst-grouped) order
    edge_kernel_csr<<<aggBlocks, 256>>>(Wm2, bm2, out);
}

// round 14
// speedup vs baseline: 2.0973x; 1.1011x over previous
#include <cuda_runtime.h>
#include <cuda_fp16.h>
#include <cstdint>

#define N_NODES 50000
#define N_EDGES 800000
#define D 256

#define BM 128
#define BN 128
#define BK 16
#define GEMM_MBLKS 391            // ceil(50000/128)

// ---------------- scratch (device globals; no allocations) ----------------
__device__ int    g_is64;
__device__ int    g_esrc[N_EDGES];
__device__ int    g_edst[N_EDGES];
__device__ int    g_deg[N_NODES];
__device__ int    g_rowptr[N_NODES + 1];
__device__ int    g_cursor[N_NODES];
__device__ int2   g_edge[N_EDGES];        // (src, eid) packed, CSR order
__device__ __half g_x16[N_NODES * D];     // fp16 copy of x
__device__ __half g_bufA[N_NODES * D];    // agg scratch, later A_pre
__device__ __half g_bufB[N_NODES * D];    // h1, later B_pre
__device__ __half g_bufC[N_NODES * D];    // h2

__device__ __forceinline__ __half* selbufh(int s) {
    if (s == 0) return g_bufA;
    if (s == 1) return g_bufB;
    if (s == 2) return g_bufC;
    return g_x16;   // 3
}

__device__ __forceinline__ uint32_t packh2(float a, float b) {
    __half2 h = __floats2half2_rn(a, b);
    return *(uint32_t*)&h;
}

// ---------------- detect dtype + zero degrees (fused) ----------------
__global__ void detect_zero_kernel(const int* __restrict__ ei32) {
    int i = blockIdx.x * blockDim.x + threadIdx.x;
    if (i < N_NODES) g_deg[i] = 0;
    if (i == 0) {
        int allzero = 1;
        for (int j = 1; j < 256; j += 2) {
            if (ei32[j] != 0) { allzero = 0; break; }
        }
        g_is64 = allzero;
    }
}

// ---------------- x -> fp16 ----------------
__global__ void convert_x_kernel(const float* __restrict__ x) {
    int i = blockIdx.x * blockDim.x + threadIdx.x;   // 8 floats per thread
    if (i >= N_NODES * D / 8) return;
    const float4* p = (const float4*)(x + (size_t)i * 8);
    float4 a = p[0], b = p[1];
    uint4 o;
    o.x = packh2(a.x, a.y); o.y = packh2(a.z, a.w);
    o.z = packh2(b.x, b.y); o.w = packh2(b.z, b.w);
    *(uint4*)(g_x16 + (size_t)i * 8) = o;
}

// ---------------- convert edge index + count degrees (fused) ----------------
__global__ void convert_count_kernel(const void* __restrict__ ei) {
    int e = blockIdx.x * blockDim.x + threadIdx.x;
    if (e >= N_EDGES) return;
    int s, d;
    if (g_is64) {
        const long long* p = (const long long*)ei;
        s = (int)p[e];
        d = (int)p[N_EDGES + e];
    } else {
        const int* p = (const int*)ei;
        s = p[e];
        d = p[N_EDGES + e];
    }
    g_esrc[e] = s;
    g_edst[e] = d;
    atomicAdd(&g_deg[d], 1);
}

__global__ void scan_kernel() {
    __shared__ int sh[1024];
    const int CH = 49;
    int t = threadIdx.x;
    int base = t * CH;
    int s = 0;
    for (int i = 0; i < CH; i++) {
        int idx = base + i;
        if (idx < N_NODES) s += g_deg[idx];
    }
    sh[t] = s;
    __syncthreads();
    for (int o = 1; o < 1024; o <<= 1) {
        int v = (t >= o) ? sh[t - o] : 0;
        __syncthreads();
        sh[t] += v;
        __syncthreads();
    }
    int run = sh[t] - s;
    for (int i = 0; i < CH; i++) {
        int idx = base + i;
        if (idx < N_NODES) {
            g_rowptr[idx] = run;
            g_cursor[idx] = run;
            run += g_deg[idx];
        }
    }
    if (t == 0) g_rowptr[N_NODES] = N_EDGES;
}

__global__ void fill_kernel() {
    int e = blockIdx.x * blockDim.x + threadIdx.x;
    if (e < N_EDGES) {
        int pos = atomicAdd(&g_cursor[g_edst[e]], 1);
        g_edge[pos] = make_int2(g_esrc[e], e);
    }
}

// ---------------- mean aggregation (fp16 in/out, fp32 accum) ----------------
// one warp per node; lane handles 8 consecutive halfs (uint4) of the row
__global__ void aggregate16_kernel(int in_sel, int out_sel) {
    const __half* in = selbufh(in_sel);
    __half* out = selbufh(out_sel);
    int gtid = blockIdx.x * blockDim.x + threadIdx.x;
    int node = gtid >> 5;
    int lane = gtid & 31;
    if (node >= N_NODES) return;
    int beg = g_rowptr[node], end = g_rowptr[node + 1];
    float acc[8] = {0.f, 0.f, 0.f, 0.f, 0.f, 0.f, 0.f, 0.f};
    for (int p = beg; p < end; p++) {
        int s = g_edge[p].x;
        uint4 v = *(const uint4*)(in + (size_t)s * D + lane * 8);
        const __half2* h = (const __half2*)&v;
#pragma unroll
        for (int j = 0; j < 4; j++) {
            float2 f = __half22float2(h[j]);
            acc[2 * j] += f.x;
            acc[2 * j + 1] += f.y;
        }
    }
    float inv = 1.f / fmaxf((float)(end - beg), 1.f);
    uint4 o;
    o.x = packh2(acc[0] * inv, acc[1] * inv);
    o.y = packh2(acc[2] * inv, acc[3] * inv);
    o.z = packh2(acc[4] * inv, acc[5] * inv);
    o.w = packh2(acc[6] * inv, acc[7] * inv);
    *(uint4*)(out + (size_t)node * D + lane * 8) = o;
}

// ---------------- fp16 tensor-core GEMM ----------------
// C[M,256] = act(A1@W1 (+ A2@W2) (+ bias)), K = 256. A inputs fp16 (node-major),
// W fp32 (packed to half2 at smem-store), C fp16. m16n8k16, 128x128 tile.
__device__ __forceinline__ void mma_f16(float* c, uint32_t a0, uint32_t a1,
                                        uint32_t a2, uint32_t a3,
                                        uint32_t b0, uint32_t b1) {
    asm volatile(
        "mma.sync.aligned.m16n8k16.row.col.f32.f16.f16.f32 "
        "{%0,%1,%2,%3}, {%4,%5,%6,%7}, {%8,%9}, {%0,%1,%2,%3};"
        : "+f"(c[0]), "+f"(c[1]), "+f"(c[2]), "+f"(c[3])
        : "r"(a0), "r"(a1), "r"(a2), "r"(a3), "r"(b0), "r"(b1));
}

template <bool DUAL, bool RELU, bool BIAS>
__device__ __forceinline__ void gemm_body(
    const __half* __restrict__ A1, const float* __restrict__ W1,
    const __half* __restrict__ A2, const float* __restrict__ W2,
    const float* __restrict__ bias, __half* __restrict__ C,
    int m0, int n0) {
    __shared__ uint32_t As[2][BM][12];        // 8 half2 cols + 4 pad
    __shared__ uint32_t Ws[2][8][BN + 8];     // 8 k-pair rows, stride 136

    const int tid = threadIdx.x;
    const int lane = tid & 31;
    const int warp = tid >> 5;
    const int wm = warp & 3;
    const int wn = warp >> 2;

    const int itersPerPass = 256 / BK;           // 16
    const int total = DUAL ? 2 * itersPerPass : itersPerPass;

    float acc[2][8][4];
#pragma unroll
    for (int i = 0; i < 2; i++)
#pragma unroll
        for (int j = 0; j < 8; j++)
#pragma unroll
            for (int r = 0; r < 4; r++) acc[i][j][r] = 0.f;

    // A tile: 128 rows x 16 k (halfs). 4 threads/row, each 4 halfs (uint2).
    const int ar0 = tid >> 2, ac0 = (tid & 3) * 4, ah0 = (tid & 3) * 2;
    const int ar1 = (tid + 256) >> 2;
    // W tile: 16 k x 128 n fp32; thread loads k rows 2wi, 2wi+1 at n-offset wn4
    const int wi = tid >> 5, wn4 = (tid & 31) * 4;

    auto loadA = [&](const __half* A, int kk, uint2& v0, uint2& v1) {
        int gm0 = m0 + ar0, gm1 = m0 + ar1;
        v0 = (gm0 < N_NODES) ? *(const uint2*)(A + (size_t)gm0 * 256 + kk + ac0)
                             : make_uint2(0u, 0u);
        v1 = (gm1 < N_NODES) ? *(const uint2*)(A + (size_t)gm1 * 256 + kk + ac0)
                             : make_uint2(0u, 0u);
    };
    auto loadW = [&](const float* W, int kk, float4& v0, float4& v1) {
        v0 = *(const float4*)(W + (size_t)(kk + 2 * wi) * 256 + n0 + wn4);
        v1 = *(const float4*)(W + (size_t)(kk + 2 * wi + 1) * 256 + n0 + wn4);
    };
    auto storeTile = [&](int buf, const uint2& a0v, const uint2& a1v,
                         const float4& w0v, const float4& w1v) {
        *(uint2*)&As[buf][ar0][ah0] = a0v;
        *(uint2*)&As[buf][ar1][ah0] = a1v;
        uint4 wp;
        wp.x = packh2(w0v.x, w1v.x);
        wp.y = packh2(w0v.y, w1v.y);
        wp.z = packh2(w0v.z, w1v.z);
        wp.w = packh2(w0v.w, w1v.w);
        *(uint4*)&Ws[buf][wi][wn4] = wp;
    };

    {
        uint2 a0v, a1v;
        float4 w0v, w1v;
        loadA(A1, 0, a0v, a1v);
        loadW(W1, 0, w0v, w1v);
        storeTile(0, a0v, a1v, w0v, w1v);
    }
    __syncthreads();

    const int mbase = wm * 32;
    const int nbase = wn * 64;
    const int fr = lane >> 2;
    const int fc = lane & 3;

    for (int it = 0; it < total; it++) {
        int buf = it & 1;
        uint2 pa0, pa1;
        float4 pw0, pw1;
        bool more = (it + 1) < total;
        if (more) {
            int nit = it + 1;
            const __half* A = (DUAL && nit >= itersPerPass) ? A2 : A1;
            const float* W = (DUAL && nit >= itersPerPass) ? W2 : W1;
            int kk = (nit & (itersPerPass - 1)) * BK;
            loadA(A, kk, pa0, pa1);
            loadW(W, kk, pw0, pw1);
        }

        uint32_t af[2][4];
#pragma unroll
        for (int mt = 0; mt < 2; mt++) {
            int r = mbase + mt * 16 + fr;
            af[mt][0] = As[buf][r][fc];
            af[mt][1] = As[buf][r + 8][fc];
            af[mt][2] = As[buf][r][fc + 4];
            af[mt][3] = As[buf][r + 8][fc + 4];
        }
        uint32_t bf[8][2];
#pragma unroll
        for (int nt = 0; nt < 8; nt++) {
            int n = nbase + nt * 8 + fr;
            bf[nt][0] = Ws[buf][fc][n];
            bf[nt][1] = Ws[buf][fc + 4][n];
        }
#pragma unroll
        for (int mt = 0; mt < 2; mt++)
#pragma unroll
            for (int nt = 0; nt < 8; nt++)
                mma_f16(acc[mt][nt], af[mt][0], af[mt][1], af[mt][2], af[mt][3],
                        bf[nt][0], bf[nt][1]);

        if (more) storeTile(buf ^ 1, pa0, pa1, pw0, pw1);
        __syncthreads();
    }

    // epilogue: write half2; c0/c1 at (fr, 2fc), c2/c3 at (fr+8, 2fc)
#pragma unroll
    for (int mt = 0; mt < 2; mt++) {
#pragma unroll
        for (int nt = 0; nt < 8; nt++) {
            int gn = n0 + nbase + nt * 8 + 2 * fc;
            float b0 = BIAS ? bias[gn] : 0.f;
            float b1 = BIAS ? bias[gn + 1] : 0.f;
            int gm0 = m0 + mbase + mt * 16 + fr;
            int gm1 = gm0 + 8;
            float2 v0, v1;
            v0.x = acc[mt][nt][0] + b0; v0.y = acc[mt][nt][1] + b1;
            v1.x = acc[mt][nt][2] + b0; v1.y = acc[mt][nt][3] + b1;
            if (RELU) {
                v0.x = fmaxf(v0.x, 0.f); v0.y = fmaxf(v0.y, 0.f);
                v1.x = fmaxf(v1.x, 0.f); v1.y = fmaxf(v1.y, 0.f);
            }
            if (gm0 < N_NODES)
                *(uint32_t*)(C + (size_t)gm0 * 256 + gn) = packh2(v0.x, v0.y);
            if (gm1 < N_NODES)
                *(uint32_t*)(C + (size_t)gm1 * 256 + gn) = packh2(v1.x, v1.y);
        }
    }
}

template <bool DUAL, bool RELU, bool BIAS>
__global__ __launch_bounds__(256, 2)
void gemm_kernel(int a1_sel, const float* __restrict__ W1,
                 int a2_sel, const float* __restrict__ W2,
                 const float* __restrict__ biasp, int c_sel) {
    gemm_body<DUAL, RELU, BIAS>(selbufh(a1_sel), W1,
                                DUAL ? selbufh(a2_sel) : nullptr, W2,
                                biasp, selbufh(c_sel),
                                blockIdx.y * BM, blockIdx.x * BN);
}

// merged edge precompute: blockIdx.x 0,1 -> bufA = h2@Wm1_top (no bias)
//                         blockIdx.x 2,3 -> bufB = h2@Wm1_bot + bm1
__global__ __launch_bounds__(256, 2)
void gemm_pre_kernel(const float* __restrict__ Wm1, const float* __restrict__ bm1) {
    int half = blockIdx.x >> 1;
    int n0 = (blockIdx.x & 1) * BN;
    const float* W = Wm1 + (size_t)half * 256 * 256;
    __half* C = half ? g_bufB : g_bufA;
    if (half)
        gemm_body<false, false, true>(g_bufC, W, nullptr, nullptr, bm1, C,
                                      blockIdx.y * BM, n0);
    else
        gemm_body<false, false, false>(g_bufC, W, nullptr, nullptr, nullptr, C,
                                       blockIdx.y * BM, n0);
}

// ---------------- edge MLP, CSR order: one warp per DST node ----------------
// out[eid] = relu(A_pre[src] + B_pre[dst]) @ [w0,w1] + bm2 ; A_pre/B_pre fp16
__global__ void edge_kernel_csr(const float* __restrict__ Wm2,
                                const float* __restrict__ bm2,
                                float* __restrict__ out) {
    __shared__ __align__(16) float w0[256];
    __shared__ __align__(16) float w1[256];
    for (int i = threadIdx.x; i < 256; i += blockDim.x) {
        w0[i] = Wm2[i * 2 + 0];
        w1[i] = Wm2[i * 2 + 1];
    }
    __syncthreads();

    int gtid = blockIdx.x * blockDim.x + threadIdx.x;
    int node = gtid >> 5;
    int lane = gtid & 31;
    if (node >= N_NODES) return;

    int beg = g_rowptr[node], end = g_rowptr[node + 1];
    if (beg == end) return;

    // B_pre[node] slice: 8 halfs for this lane -> fp32 regs
    float b[8];
    {
        uint4 bv = *(const uint4*)(g_bufB + (size_t)node * D + lane * 8);
        const __half2* h = (const __half2*)&bv;
#pragma unroll
        for (int j = 0; j < 4; j++) {
            float2 f = __half22float2(h[j]);
            b[2 * j] = f.x;
            b[2 * j + 1] = f.y;
        }
    }
    // weights: contiguous 8 per lane (dot is order-invariant)
    float wa[8], wb[8];
    {
        const float4* w0f = (const float4*)w0;
        const float4* w1f = (const float4*)w1;
        float4 t0 = w0f[lane * 2], t1 = w0f[lane * 2 + 1];
        wa[0] = t0.x; wa[1] = t0.y; wa[2] = t0.z; wa[3] = t0.w;
        wa[4] = t1.x; wa[5] = t1.y; wa[6] = t1.z; wa[7] = t1.w;
        float4 s0 = w1f[lane * 2], s1 = w1f[lane * 2 + 1];
        wb[0] = s0.x; wb[1] = s0.y; wb[2] = s0.z; wb[3] = s0.w;
        wb[4] = s1.x; wb[5] = s1.y; wb[6] = s1.z; wb[7] = s1.w;
    }

    float bias0 = bm2[0], bias1 = bm2[1];

    for (int p = beg; p < end; p++) {
        int2 se = g_edge[p];
        int s = se.x;
        int eid = se.y;
        uint4 av = *(const uint4*)(g_bufA + (size_t)s * D + lane * 8);
        const __half2* h = (const __half2*)&av;

        float acc0 = 0.f, acc1 = 0.f;
#pragma unroll
        for (int j = 0; j < 4; j++) {
            float2 f = __half22float2(h[j]);
            float v0 = fmaxf(f.x + b[2 * j], 0.f);
            float v1 = fmaxf(f.y + b[2 * j + 1], 0.f);
            acc0 = fmaf(v0, wa[2 * j], acc0);
            acc0 = fmaf(v1, wa[2 * j + 1], acc0);
            acc1 = fmaf(v0, wb[2 * j], acc1);
            acc1 = fmaf(v1, wb[2 * j + 1], acc1);
        }

#pragma unroll
        for (int o = 16; o > 0; o >>= 1) {
            acc0 += __shfl_xor_sync(0xFFFFFFFFu, acc0, o);
            acc1 += __shfl_xor_sync(0xFFFFFFFFu, acc1, o);
        }
        if (lane == 0) {
            float2 r;
            r.x = acc0 + bias0;
            r.y = acc1 + bias1;
            *(float2*)(out + (size_t)eid * 2) = r;
        }
    }
}

// ---------------- launch ----------------
extern "C" void kernel_launch(void* const* d_in, const int* in_sizes, int n_in,
                              void* d_out, int out_size) {
    const float* x   = (const float*)d_in[0];
    const void*  ei  = d_in[1];
    const float* W1l = (const float*)d_in[2];
    const float* b1l = (const float*)d_in[3];
    const float* W1r = (const float*)d_in[4];
    const float* W2l = (const float*)d_in[5];
    const float* b2l = (const float*)d_in[6];
    const float* W2r = (const float*)d_in[7];
    const float* Wm1 = (const float*)d_in[8];
    const float* bm1 = (const float*)d_in[9];
    const float* Wm2 = (const float*)d_in[10];
    const float* bm2 = (const float*)d_in[11];
    float* out = (float*)d_out;

    // dtype detect + zero degrees; x->fp16; edge convert + count; CSR
    detect_zero_kernel<<<(N_NODES + 255) / 256, 256>>>((const int*)ei);
    convert_x_kernel<<<(N_NODES * D / 8 + 255) / 256, 256>>>(x);
    convert_count_kernel<<<(N_EDGES + 255) / 256, 256>>>(ei);
    scan_kernel<<<1, 1024>>>();
    fill_kernel<<<(N_EDGES + 255) / 256, 256>>>();

    dim3 ggrid(2, GEMM_MBLKS);
    dim3 pgrid(4, GEMM_MBLKS);
    int aggBlocks = (N_NODES * 32 + 255) / 256;

    // layer 1: agg(x16) -> bufA ; h1 = relu(agg@W1l + x16@W1r + b1l) -> bufB
    aggregate16_kernel<<<aggBlocks, 256>>>(3, 0);
    gemm_kernel<true, true, true><<<ggrid, 256>>>(0, W1l, 3, W1r, b1l, 1);

    // layer 2: agg(h1) -> bufA ; h2 = relu(agg@W2l + h1@W2r + b2l) -> bufC
    aggregate16_kernel<<<aggBlocks, 256>>>(1, 0);
    gemm_kernel<true, true, true><<<ggrid, 256>>>(0, W2l, 1, W2r, b2l, 2);

    // merged edge precompute: bufA = h2@Wm1_top ; bufB = h2@Wm1_bot + bm1
    gemm_pre_kernel<<<pgrid, 256>>>(Wm1, bm1);

    // edge MLP in CSR (dst-grouped) order
    edge_kernel_csr<<<aggBlocks, 256>>>(Wm2, bm2, out);
}

// round 15
// speedup vs baseline: 2.4414x; 1.1641x over previous
#include <cuda_runtime.h>
#include <cuda_fp16.h>
#include <cstdint>

#define N_NODES 50000
#define N_EDGES 800000
#define D 256

#define BM 128
#define BN 128
#define BK 16
#define GEMM_MBLKS 391            // ceil(50000/128)
#define SCAN_BLOCKS 49            // ceil(50000/1024)

// ---------------- scratch (device globals; no allocations) ----------------
__device__ int    g_is64;
__device__ int    g_esrc[N_EDGES];
__device__ int    g_edst[N_EDGES];
__device__ int    g_deg[N_NODES];
__device__ int    g_bsum[SCAN_BLOCKS];
__device__ int    g_rowptr[N_NODES + 1];
__device__ int    g_cursor[N_NODES];
__device__ int2   g_edge[N_EDGES];        // (src, eid) packed, CSR order
__device__ __half g_x16[N_NODES * D];     // fp16 copy of x
__device__ __half g_bufA[N_NODES * D];    // agg scratch, later A_pre
__device__ __half g_bufB[N_NODES * D];    // h1, later B_pre
__device__ __half g_bufC[N_NODES * D];    // h2

__device__ __forceinline__ __half* selbufh(int s) {
    if (s == 0) return g_bufA;
    if (s == 1) return g_bufB;
    if (s == 2) return g_bufC;
    return g_x16;   // 3
}

__device__ __forceinline__ uint32_t packh2(float a, float b) {
    __half2 h = __floats2half2_rn(a, b);
    return *(uint32_t*)&h;
}

// ---------------- detect dtype + zero degrees (fused) ----------------
__global__ void detect_zero_kernel(const int* __restrict__ ei32) {
    int i = blockIdx.x * blockDim.x + threadIdx.x;
    if (i < N_NODES) g_deg[i] = 0;
    if (i == 0) {
        int allzero = 1;
        for (int j = 1; j < 256; j += 2) {
            if (ei32[j] != 0) { allzero = 0; break; }
        }
        g_is64 = allzero;
    }
}

// ---------------- x -> fp16 ----------------
__global__ void convert_x_kernel(const float* __restrict__ x) {
    int i = blockIdx.x * blockDim.x + threadIdx.x;   // 8 floats per thread
    if (i >= N_NODES * D / 8) return;
    const float4* p = (const float4*)(x + (size_t)i * 8);
    float4 a = p[0], b = p[1];
    uint4 o;
    o.x = packh2(a.x, a.y); o.y = packh2(a.z, a.w);
    o.z = packh2(b.x, b.y); o.w = packh2(b.z, b.w);
    *(uint4*)(g_x16 + (size_t)i * 8) = o;
}

// ---------------- convert edge index + count degrees (fused) ----------------
__global__ void convert_count_kernel(const void* __restrict__ ei) {
    int e = blockIdx.x * blockDim.x + threadIdx.x;
    if (e >= N_EDGES) return;
    int s, d;
    if (g_is64) {
        const long long* p = (const long long*)ei;
        s = (int)p[e];
        d = (int)p[N_EDGES + e];
    } else {
        const int* p = (const int*)ei;
        s = p[e];
        d = p[N_EDGES + e];
    }
    g_esrc[e] = s;
    g_edst[e] = d;
    atomicAdd(&g_deg[d], 1);
}

// ---------------- parallel CSR prefix scan (3 phases) ----------------
// Phase 1: per-block degree sums (49 blocks x 1024)
__global__ void block_reduce_kernel() {
    __shared__ int sh[32];
    int i = blockIdx.x * 1024 + threadIdx.x;
    int v = (i < N_NODES) ? g_deg[i] : 0;
#pragma unroll
    for (int o = 16; o > 0; o >>= 1) v += __shfl_xor_sync(0xFFFFFFFFu, v, o);
    if ((threadIdx.x & 31) == 0) sh[threadIdx.x >> 5] = v;
    __syncthreads();
    if (threadIdx.x < 32) {
        int w = sh[threadIdx.x];
#pragma unroll
        for (int o = 16; o > 0; o >>= 1) w += __shfl_xor_sync(0xFFFFFFFFu, w, o);
        if (threadIdx.x == 0) g_bsum[blockIdx.x] = w;
    }
}

// Phase 2: exclusive scan of the 49 block sums (1 block x 64)
__global__ void scan_bsum_kernel() {
    __shared__ int sh[64];
    int t = threadIdx.x;
    int v = (t < SCAN_BLOCKS) ? g_bsum[t] : 0;
    sh[t] = v;
    __syncthreads();
    for (int o = 1; o < 64; o <<= 1) {
        int u = (t >= o) ? sh[t - o] : 0;
        __syncthreads();
        sh[t] += u;
        __syncthreads();
    }
    if (t < SCAN_BLOCKS) g_bsum[t] = sh[t] - v;   // exclusive prefix
}

// Phase 3: in-block scan + offset -> rowptr/cursor (49 blocks x 1024)
__global__ void block_scan_kernel() {
    __shared__ int sh[1024];
    int t = threadIdx.x;
    int i = blockIdx.x * 1024 + t;
    int v = (i < N_NODES) ? g_deg[i] : 0;
    sh[t] = v;
    __syncthreads();
    for (int o = 1; o < 1024; o <<= 1) {
        int u = (t >= o) ? sh[t - o] : 0;
        __syncthreads();
        sh[t] += u;
        __syncthreads();
    }
    if (i < N_NODES) {
        int run = g_bsum[blockIdx.x] + sh[t] - v;   // exclusive
        g_rowptr[i] = run;
        g_cursor[i] = run;
    }
    if (blockIdx.x == 0 && t == 0) g_rowptr[N_NODES] = N_EDGES;
}

__global__ void fill_kernel() {
    int e = blockIdx.x * blockDim.x + threadIdx.x;
    if (e < N_EDGES) {
        int pos = atomicAdd(&g_cursor[g_edst[e]], 1);
        g_edge[pos] = make_int2(g_esrc[e], e);
    }
}

// ---------------- mean aggregation (fp16 in/out, fp32 accum) ----------------
__global__ void aggregate16_kernel(int in_sel, int out_sel) {
    const __half* in = selbufh(in_sel);
    __half* out = selbufh(out_sel);
    int gtid = blockIdx.x * blockDim.x + threadIdx.x;
    int node = gtid >> 5;
    int lane = gtid & 31;
    if (node >= N_NODES) return;
    int beg = g_rowptr[node], end = g_rowptr[node + 1];
    float acc[8] = {0.f, 0.f, 0.f, 0.f, 0.f, 0.f, 0.f, 0.f};
    for (int p = beg; p < end; p++) {
        int s = g_edge[p].x;
        uint4 v = *(const uint4*)(in + (size_t)s * D + lane * 8);
        const __half2* h = (const __half2*)&v;
#pragma unroll
        for (int j = 0; j < 4; j++) {
            float2 f = __half22float2(h[j]);
            acc[2 * j] += f.x;
            acc[2 * j + 1] += f.y;
        }
    }
    float inv = 1.f / fmaxf((float)(end - beg), 1.f);
    uint4 o;
    o.x = packh2(acc[0] * inv, acc[1] * inv);
    o.y = packh2(acc[2] * inv, acc[3] * inv);
    o.z = packh2(acc[4] * inv, acc[5] * inv);
    o.w = packh2(acc[6] * inv, acc[7] * inv);
    *(uint4*)(out + (size_t)node * D + lane * 8) = o;
}

// ---------------- fp16 tensor-core GEMM ----------------
__device__ __forceinline__ void mma_f16(float* c, uint32_t a0, uint32_t a1,
                                        uint32_t a2, uint32_t a3,
                                        uint32_t b0, uint32_t b1) {
    asm volatile(
        "mma.sync.aligned.m16n8k16.row.col.f32.f16.f16.f32 "
        "{%0,%1,%2,%3}, {%4,%5,%6,%7}, {%8,%9}, {%0,%1,%2,%3};"
        : "+f"(c[0]), "+f"(c[1]), "+f"(c[2]), "+f"(c[3])
        : "r"(a0), "r"(a1), "r"(a2), "r"(a3), "r"(b0), "r"(b1));
}

template <bool DUAL, bool RELU, bool BIAS>
__device__ __forceinline__ void gemm_body(
    const __half* __restrict__ A1, const float* __restrict__ W1,
    const __half* __restrict__ A2, const float* __restrict__ W2,
    const float* __restrict__ bias, __half* __restrict__ C,
    int m0, int n0) {
    __shared__ uint32_t As[2][BM][12];        // 8 half2 cols + 4 pad
    __shared__ uint32_t Ws[2][8][BN + 8];     // 8 k-pair rows, stride 136

    const int tid = threadIdx.x;
    const int lane = tid & 31;
    const int warp = tid >> 5;
    const int wm = warp & 3;
    const int wn = warp >> 2;

    const int itersPerPass = 256 / BK;           // 16
    const int total = DUAL ? 2 * itersPerPass : itersPerPass;

    float acc[2][8][4];
#pragma unroll
    for (int i = 0; i < 2; i++)
#pragma unroll
        for (int j = 0; j < 8; j++)
#pragma unroll
            for (int r = 0; r < 4; r++) acc[i][j][r] = 0.f;

    const int ar0 = tid >> 2, ac0 = (tid & 3) * 4, ah0 = (tid & 3) * 2;
    const int ar1 = (tid + 256) >> 2;
    const int wi = tid >> 5, wn4 = (tid & 31) * 4;

    auto loadA = [&](const __half* A, int kk, uint2& v0, uint2& v1) {
        int gm0 = m0 + ar0, gm1 = m0 + ar1;
        v0 = (gm0 < N_NODES) ? *(const uint2*)(A + (size_t)gm0 * 256 + kk + ac0)
                             : make_uint2(0u, 0u);
        v1 = (gm1 < N_NODES) ? *(const uint2*)(A + (size_t)gm1 * 256 + kk + ac0)
                             : make_uint2(0u, 0u);
    };
    auto loadW = [&](const float* W, int kk, float4& v0, float4& v1) {
        v0 = *(const float4*)(W + (size_t)(kk + 2 * wi) * 256 + n0 + wn4);
        v1 = *(const float4*)(W + (size_t)(kk + 2 * wi + 1) * 256 + n0 + wn4);
    };
    auto storeTile = [&](int buf, const uint2& a0v, const uint2& a1v,
                         const float4& w0v, const float4& w1v) {
        *(uint2*)&As[buf][ar0][ah0] = a0v;
        *(uint2*)&As[buf][ar1][ah0] = a1v;
        uint4 wp;
        wp.x = packh2(w0v.x, w1v.x);
        wp.y = packh2(w0v.y, w1v.y);
        wp.z = packh2(w0v.z, w1v.z);
        wp.w = packh2(w0v.w, w1v.w);
        *(uint4*)&Ws[buf][wi][wn4] = wp;
    };

    {
        uint2 a0v, a1v;
        float4 w0v, w1v;
        loadA(A1, 0, a0v, a1v);
        loadW(W1, 0, w0v, w1v);
        storeTile(0, a0v, a1v, w0v, w1v);
    }
    __syncthreads();

    const int mbase = wm * 32;
    const int nbase = wn * 64;
    const int fr = lane >> 2;
    const int fc = lane & 3;

    for (int it = 0; it < total; it++) {
        int buf = it & 1;
        uint2 pa0, pa1;
        float4 pw0, pw1;
        bool more = (it + 1) < total;
        if (more) {
            int nit = it + 1;
            const __half* A = (DUAL && nit >= itersPerPass) ? A2 : A1;
            const float* W = (DUAL && nit >= itersPerPass) ? W2 : W1;
            int kk = (nit & (itersPerPass - 1)) * BK;
            loadA(A, kk, pa0, pa1);
            loadW(W, kk, pw0, pw1);
        }

        uint32_t af[2][4];
#pragma unroll
        for (int mt = 0; mt < 2; mt++) {
            int r = mbase + mt * 16 + fr;
            af[mt][0] = As[buf][r][fc];
            af[mt][1] = As[buf][r + 8][fc];
            af[mt][2] = As[buf][r][fc + 4];
            af[mt][3] = As[buf][r + 8][fc + 4];
        }
        uint32_t bf[8][2];
#pragma unroll
        for (int nt = 0; nt < 8; nt++) {
            int n = nbase + nt * 8 + fr;
            bf[nt][0] = Ws[buf][fc][n];
            bf[nt][1] = Ws[buf][fc + 4][n];
        }
#pragma unroll
        for (int mt = 0; mt < 2; mt++)
#pragma unroll
            for (int nt = 0; nt < 8; nt++)
                mma_f16(acc[mt][nt], af[mt][0], af[mt][1], af[mt][2], af[mt][3],
                        bf[nt][0], bf[nt][1]);

        if (more) storeTile(buf ^ 1, pa0, pa1, pw0, pw1);
        __syncthreads();
    }

    // epilogue: write half2
#pragma unroll
    for (int mt = 0; mt < 2; mt++) {
#pragma unroll
        for (int nt = 0; nt < 8; nt++) {
            int gn = n0 + nbase + nt * 8 + 2 * fc;
            float b0 = BIAS ? bias[gn] : 0.f;
            float b1 = BIAS ? bias[gn + 1] : 0.f;
            int gm0 = m0 + mbase + mt * 16 + fr;
            int gm1 = gm0 + 8;
            float2 v0, v1;
            v0.x = acc[mt][nt][0] + b0; v0.y = acc[mt][nt][1] + b1;
            v1.x = acc[mt][nt][2] + b0; v1.y = acc[mt][nt][3] + b1;
            if (RELU) {
                v0.x = fmaxf(v0.x, 0.f); v0.y = fmaxf(v0.y, 0.f);
                v1.x = fmaxf(v1.x, 0.f); v1.y = fmaxf(v1.y, 0.f);
            }
            if (gm0 < N_NODES)
                *(uint32_t*)(C + (size_t)gm0 * 256 + gn) = packh2(v0.x, v0.y);
            if (gm1 < N_NODES)
                *(uint32_t*)(C + (size_t)gm1 * 256 + gn) = packh2(v1.x, v1.y);
        }
    }
}

template <bool DUAL, bool RELU, bool BIAS>
__global__ __launch_bounds__(256, 2)
void gemm_kernel(int a1_sel, const float* __restrict__ W1,
                 int a2_sel, const float* __restrict__ W2,
                 const float* __restrict__ biasp, int c_sel) {
    gemm_body<DUAL, RELU, BIAS>(selbufh(a1_sel), W1,
                                DUAL ? selbufh(a2_sel) : nullptr, W2,
                                biasp, selbufh(c_sel),
                                blockIdx.y * BM, blockIdx.x * BN);
}

// merged edge precompute
__global__ __launch_bounds__(256, 2)
void gemm_pre_kernel(const float* __restrict__ Wm1, const float* __restrict__ bm1) {
    int half = blockIdx.x >> 1;
    int n0 = (blockIdx.x & 1) * BN;
    const float* W = Wm1 + (size_t)half * 256 * 256;
    __half* C = half ? g_bufB : g_bufA;
    if (half)
        gemm_body<false, false, true>(g_bufC, W, nullptr, nullptr, bm1, C,
                                      blockIdx.y * BM, n0);
    else
        gemm_body<false, false, false>(g_bufC, W, nullptr, nullptr, nullptr, C,
                                       blockIdx.y * BM, n0);
}

// ---------------- edge MLP, CSR order: one warp per DST node ----------------
__global__ void edge_kernel_csr(const float* __restrict__ Wm2,
                                const float* __restrict__ bm2,
                                float* __restrict__ out) {
    __shared__ __align__(16) float w0[256];
    __shared__ __align__(16) float w1[256];
    for (int i = threadIdx.x; i < 256; i += blockDim.x) {
        w0[i] = Wm2[i * 2 + 0];
        w1[i] = Wm2[i * 2 + 1];
    }
    __syncthreads();

    int gtid = blockIdx.x * blockDim.x + threadIdx.x;
    int node = gtid >> 5;
    int lane = gtid & 31;
    if (node >= N_NODES) return;

    int beg = g_rowptr[node], end = g_rowptr[node + 1];
    if (beg == end) return;

    float b[8];
    {
        uint4 bv = *(const uint4*)(g_bufB + (size_t)node * D + lane * 8);
        const __half2* h = (const __half2*)&bv;
#pragma unroll
        for (int j = 0; j < 4; j++) {
            float2 f = __half22float2(h[j]);
            b[2 * j] = f.x;
            b[2 * j + 1] = f.y;
        }
    }
    float wa[8], wb[8];
    {
        const float4* w0f = (const float4*)w0;
        const float4* w1f = (const float4*)w1;
        float4 t0 = w0f[lane * 2], t1 = w0f[lane * 2 + 1];
        wa[0] = t0.x; wa[1] = t0.y; wa[2] = t0.z; wa[3] = t0.w;
        wa[4] = t1.x; wa[5] = t1.y; wa[6] = t1.z; wa[7] = t1.w;
        float4 s0 = w1f[lane * 2], s1 = w1f[lane * 2 + 1];
        wb[0] = s0.x; wb[1] = s0.y; wb[2] = s0.z; wb[3] = s0.w;
        wb[4] = s1.x; wb[5] = s1.y; wb[6] = s1.z; wb[7] = s1.w;
    }

    float bias0 = bm2[0], bias1 = bm2[1];

    for (int p = beg; p < end; p++) {
        int2 se = g_edge[p];
        int s = se.x;
        int eid = se.y;
        uint4 av = *(const uint4*)(g_bufA + (size_t)s * D + lane * 8);
        const __half2* h = (const __half2*)&av;

        float acc0 = 0.f, acc1 = 0.f;
#pragma unroll
        for (int j = 0; j < 4; j++) {
            float2 f = __half22float2(h[j]);
            float v0 = fmaxf(f.x + b[2 * j], 0.f);
            float v1 = fmaxf(f.y + b[2 * j + 1], 0.f);
            acc0 = fmaf(v0, wa[2 * j], acc0);
            acc0 = fmaf(v1, wa[2 * j + 1], acc0);
            acc1 = fmaf(v0, wb[2 * j], acc1);
            acc1 = fmaf(v1, wb[2 * j + 1], acc1);
        }

#pragma unroll
        for (int o = 16; o > 0; o >>= 1) {
            acc0 += __shfl_xor_sync(0xFFFFFFFFu, acc0, o);
            acc1 += __shfl_xor_sync(0xFFFFFFFFu, acc1, o);
        }
        if (lane == 0) {
            float2 r;
            r.x = acc0 + bias0;
            r.y = acc1 + bias1;
            *(float2*)(out + (size_t)eid * 2) = r;
        }
    }
}

// ---------------- launch ----------------
extern "C" void kernel_launch(void* const* d_in, const int* in_sizes, int n_in,
                              void* d_out, int out_size) {
    const float* x   = (const float*)d_in[0];
    const void*  ei  = d_in[1];
    const float* W1l = (const float*)d_in[2];
    const float* b1l = (const float*)d_in[3];
    const float* W1r = (const float*)d_in[4];
    const float* W2l = (const float*)d_in[5];
    const float* b2l = (const float*)d_in[6];
    const float* W2r = (const float*)d_in[7];
    const float* Wm1 = (const float*)d_in[8];
    const float* bm1 = (const float*)d_in[9];
    const float* Wm2 = (const float*)d_in[10];
    const float* bm2 = (const float*)d_in[11];
    float* out = (float*)d_out;

    // dtype detect + zero degrees; x->fp16; edge convert + count
    detect_zero_kernel<<<(N_NODES + 255) / 256, 256>>>((const int*)ei);
    convert_x_kernel<<<(N_NODES * D / 8 + 255) / 256, 256>>>(x);
    convert_count_kernel<<<(N_EDGES + 255) / 256, 256>>>(ei);

    // parallel CSR scan (3 phases) + fill
    block_reduce_kernel<<<SCAN_BLOCKS, 1024>>>();
    scan_bsum_kernel<<<1, 64>>>();
    block_scan_kernel<<<SCAN_BLOCKS, 1024>>>();
    fill_kernel<<<(N_EDGES + 255) / 256, 256>>>();

    dim3 ggrid(2, GEMM_MBLKS);
    dim3 pgrid(4, GEMM_MBLKS);
    int aggBlocks = (N_NODES * 32 + 255) / 256;

    // layer 1: agg(x16) -> bufA ; h1 = relu(agg@W1l + x16@W1r + b1l) -> bufB
    aggregate16_kernel<<<aggBlocks, 256>>>(3, 0);
    gemm_kernel<true, true, true><<<ggrid, 256>>>(0, W1l, 3, W1r, b1l, 1);

    // layer 2: agg(h1) -> bufA ; h2 = relu(agg@W2l + h1@W2r + b2l) -> bufC
    aggregate16_kernel<<<aggBlocks, 256>>>(1, 0);
    gemm_kernel<true, true, true><<<ggrid, 256>>>(0, W2l, 1, W2r, b2l, 2);

    // merged edge precompute: bufA = h2@Wm1_top ; bufB = h2@Wm1_bot + bm1
    gemm_pre_kernel<<<pgrid, 256>>>(Wm1, bm1);

    // edge MLP in CSR (dst-grouped) order
    edge_kernel_csr<<<aggBlocks, 256>>>(Wm2, bm2, out);
}

// round 16
// speedup vs baseline: 2.5183x; 1.0315x over previous
#include <cuda_runtime.h>
#include <cuda_fp16.h>
#include <cstdint>

#define N_NODES 50000
#define N_EDGES 800000
#define D 256

#define BM 128
#define BN 128
#define BK 16
#define GEMM_MBLKS 391            // ceil(50000/128)
#define SCAN_BLOCKS 49            // ceil(50000/1024)
#define WSLOT 32768               // half2 per weight panel (256*256/2)

// ---------------- scratch (device globals; no allocations) ----------------
__device__ int      g_is64;
__device__ int      g_deg[N_NODES];
__device__ int      g_bsum[SCAN_BLOCKS];
__device__ int      g_rowptr[N_NODES + 1];
__device__ int      g_cursor[N_NODES];
__device__ int2     g_edge[N_EDGES];        // (src, eid) packed, CSR order
__device__ uint32_t g_w16[6 * WSLOT];       // fp16 weights, k-pair interleaved
__device__ __half   g_x16[N_NODES * D];     // fp16 copy of x
__device__ __half   g_bufA[N_NODES * D];    // agg scratch, later A_pre
__device__ __half   g_bufB[N_NODES * D];    // h1, later B_pre
__device__ __half   g_bufC[N_NODES * D];    // h2

__device__ __forceinline__ __half* selbufh(int s) {
    if (s == 0) return g_bufA;
    if (s == 1) return g_bufB;
    if (s == 2) return g_bufC;
    return g_x16;   // 3
}

__device__ __forceinline__ uint32_t packh2(float a, float b) {
    __half2 h = __floats2half2_rn(a, b);
    return *(uint32_t*)&h;
}

__device__ __forceinline__ int dec_dst(const void* ei, int e) {
    return g_is64 ? (int)((const long long*)ei)[N_EDGES + e]
                  : ((const int*)ei)[N_EDGES + e];
}
__device__ __forceinline__ int dec_src(const void* ei, int e) {
    return g_is64 ? (int)((const long long*)ei)[e]
                  : ((const int*)ei)[e];
}

// ---------------- detect dtype + zero degrees (fused) ----------------
__global__ void detect_zero_kernel(const int* __restrict__ ei32) {
    int i = blockIdx.x * blockDim.x + threadIdx.x;
    if (i < N_NODES) g_deg[i] = 0;
    if (i == 0) {
        int allzero = 1;
        for (int j = 1; j < 256; j += 2) {
            if (ei32[j] != 0) { allzero = 0; break; }
        }
        g_is64 = allzero;
    }
}

// ---------------- x -> fp16 ----------------
__global__ void convert_x_kernel(const float* __restrict__ x) {
    int i = blockIdx.x * blockDim.x + threadIdx.x;   // 8 floats per thread
    if (i >= N_NODES * D / 8) return;
    const float4* p = (const float4*)(x + (size_t)i * 8);
    float4 a = p[0], b = p[1];
    uint4 o;
    o.x = packh2(a.x, a.y); o.y = packh2(a.z, a.w);
    o.z = packh2(b.x, b.y); o.w = packh2(b.z, b.w);
    *(uint4*)(g_x16 + (size_t)i * 8) = o;
}

// ---------------- weights -> fp16, k-pair interleaved ----------------
// g_w16[slot*WSLOT + kp*256 + n] = half2(W[2kp][n], W[2kp+1][n])
// grid (128, 6), block 256. Wm1 occupies slots 4 (top half) and 5 (bottom).
__global__ void convert_w_kernel(const float* __restrict__ W1l,
                                 const float* __restrict__ W1r,
                                 const float* __restrict__ W2l,
                                 const float* __restrict__ W2r,
                                 const float* __restrict__ Wm1) {
    int slot = blockIdx.y;
    const float* W;
    if (slot == 0) W = W1l;
    else if (slot == 1) W = W1r;
    else if (slot == 2) W = W2l;
    else if (slot == 3) W = W2r;
    else if (slot == 4) W = Wm1;
    else W = Wm1 + 256 * 256;
    int kp = blockIdx.x;
    int n = threadIdx.x;
    float lo = W[(size_t)(2 * kp) * 256 + n];
    float hi = W[(size_t)(2 * kp + 1) * 256 + n];
    g_w16[slot * WSLOT + kp * 256 + n] = packh2(lo, hi);
}

// ---------------- degree count (direct edge decode) ----------------
__global__ void count_kernel(const void* __restrict__ ei) {
    int e = blockIdx.x * blockDim.x + threadIdx.x;
    if (e < N_EDGES) atomicAdd(&g_deg[dec_dst(ei, e)], 1);
}

// ---------------- parallel CSR prefix scan (3 phases) ----------------
__global__ void block_reduce_kernel() {
    __shared__ int sh[32];
    int i = blockIdx.x * 1024 + threadIdx.x;
    int v = (i < N_NODES) ? g_deg[i] : 0;
#pragma unroll
    for (int o = 16; o > 0; o >>= 1) v += __shfl_xor_sync(0xFFFFFFFFu, v, o);
    if ((threadIdx.x & 31) == 0) sh[threadIdx.x >> 5] = v;
    __syncthreads();
    if (threadIdx.x < 32) {
        int w = sh[threadIdx.x];
#pragma unroll
        for (int o = 16; o > 0; o >>= 1) w += __shfl_xor_sync(0xFFFFFFFFu, w, o);
        if (threadIdx.x == 0) g_bsum[blockIdx.x] = w;
    }
}

__global__ void scan_bsum_kernel() {
    __shared__ int sh[64];
    int t = threadIdx.x;
    int v = (t < SCAN_BLOCKS) ? g_bsum[t] : 0;
    sh[t] = v;
    __syncthreads();
    for (int o = 1; o < 64; o <<= 1) {
        int u = (t >= o) ? sh[t - o] : 0;
        __syncthreads();
        sh[t] += u;
        __syncthreads();
    }
    if (t < SCAN_BLOCKS) g_bsum[t] = sh[t] - v;   // exclusive prefix
}

__global__ void block_scan_kernel() {
    __shared__ int sh[1024];
    int t = threadIdx.x;
    int i = blockIdx.x * 1024 + t;
    int v = (i < N_NODES) ? g_deg[i] : 0;
    sh[t] = v;
    __syncthreads();
    for (int o = 1; o < 1024; o <<= 1) {
        int u = (t >= o) ? sh[t - o] : 0;
        __syncthreads();
        sh[t] += u;
        __syncthreads();
    }
    if (i < N_NODES) {
        int run = g_bsum[blockIdx.x] + sh[t] - v;   // exclusive
        g_rowptr[i] = run;
        g_cursor[i] = run;
    }
    if (blockIdx.x == 0 && t == 0) g_rowptr[N_NODES] = N_EDGES;
}

__global__ void fill_kernel(const void* __restrict__ ei) {
    int e = blockIdx.x * blockDim.x + threadIdx.x;
    if (e < N_EDGES) {
        int d = dec_dst(ei, e);
        int s = dec_src(ei, e);
        int pos = atomicAdd(&g_cursor[d], 1);
        g_edge[pos] = make_int2(s, e);
    }
}

// ---------------- mean aggregation (fp16 in/out, fp32 accum) ----------------
__global__ void aggregate16_kernel(int in_sel, int out_sel) {
    const __half* in = selbufh(in_sel);
    __half* out = selbufh(out_sel);
    int gtid = blockIdx.x * blockDim.x + threadIdx.x;
    int node = gtid >> 5;
    int lane = gtid & 31;
    if (node >= N_NODES) return;
    int beg = g_rowptr[node], end = g_rowptr[node + 1];
    float acc[8] = {0.f, 0.f, 0.f, 0.f, 0.f, 0.f, 0.f, 0.f};
    for (int p = beg; p < end; p++) {
        int s = g_edge[p].x;
        uint4 v = *(const uint4*)(in + (size_t)s * D + lane * 8);
        const __half2* h = (const __half2*)&v;
#pragma unroll
        for (int j = 0; j < 4; j++) {
            float2 f = __half22float2(h[j]);
            acc[2 * j] += f.x;
            acc[2 * j + 1] += f.y;
        }
    }
    float inv = 1.f / fmaxf((float)(end - beg), 1.f);
    uint4 o;
    o.x = packh2(acc[0] * inv, acc[1] * inv);
    o.y = packh2(acc[2] * inv, acc[3] * inv);
    o.z = packh2(acc[4] * inv, acc[5] * inv);
    o.w = packh2(acc[6] * inv, acc[7] * inv);
    *(uint4*)(out + (size_t)node * D + lane * 8) = o;
}

// ---------------- fp16 tensor-core GEMM ----------------
__device__ __forceinline__ void mma_f16(float* c, uint32_t a0, uint32_t a1,
                                        uint32_t a2, uint32_t a3,
                                        uint32_t b0, uint32_t b1) {
    asm volatile(
        "mma.sync.aligned.m16n8k16.row.col.f32.f16.f16.f32 "
        "{%0,%1,%2,%3}, {%4,%5,%6,%7}, {%8,%9}, {%0,%1,%2,%3};"
        : "+f"(c[0]), "+f"(c[1]), "+f"(c[2]), "+f"(c[3])
        : "r"(a0), "r"(a1), "r"(a2), "r"(a3), "r"(b0), "r"(b1));
}

// Weights come pre-packed fp16 from g_w16 (slot index), A fp16 node-major.
template <bool DUAL, bool RELU, bool BIAS>
__device__ __forceinline__ void gemm_body(
    const __half* __restrict__ A1, int w1_slot,
    const __half* __restrict__ A2, int w2_slot,
    const float* __restrict__ bias, __half* __restrict__ C,
    int m0, int n0) {
    __shared__ uint32_t As[2][BM][12];        // 8 half2 cols + 4 pad
    __shared__ uint32_t Ws[2][8][BN + 8];     // 8 k-pair rows, stride 136

    const int tid = threadIdx.x;
    const int lane = tid & 31;
    const int warp = tid >> 5;
    const int wm = warp & 3;
    const int wn = warp >> 2;

    const int itersPerPass = 256 / BK;           // 16
    const int total = DUAL ? 2 * itersPerPass : itersPerPass;

    float acc[2][8][4];
#pragma unroll
    for (int i = 0; i < 2; i++)
#pragma unroll
        for (int j = 0; j < 8; j++)
#pragma unroll
            for (int r = 0; r < 4; r++) acc[i][j][r] = 0.f;

    const int ar0 = tid >> 2, ac0 = (tid & 3) * 4, ah0 = (tid & 3) * 2;
    const int ar1 = (tid + 256) >> 2;
    const int wi = tid >> 5, wn4 = (tid & 31) * 4;

    auto loadA = [&](const __half* A, int kk, uint2& v0, uint2& v1) {
        int gm0 = m0 + ar0, gm1 = m0 + ar1;
        v0 = (gm0 < N_NODES) ? *(const uint2*)(A + (size_t)gm0 * 256 + kk + ac0)
                             : make_uint2(0u, 0u);
        v1 = (gm1 < N_NODES) ? *(const uint2*)(A + (size_t)gm1 * 256 + kk + ac0)
                             : make_uint2(0u, 0u);
    };
    auto loadW = [&](int slot, int kk, uint4& v) {
        const uint32_t* Wp = g_w16 + slot * WSLOT;
        v = *(const uint4*)(Wp + (kk / 2 + wi) * 256 + n0 + wn4);
    };
    auto storeTile = [&](int buf, const uint2& a0v, const uint2& a1v,
                         const uint4& wv) {
        *(uint2*)&As[buf][ar0][ah0] = a0v;
        *(uint2*)&As[buf][ar1][ah0] = a1v;
        *(uint4*)&Ws[buf][wi][wn4] = wv;
    };

    {
        uint2 a0v, a1v;
        uint4 wv;
        loadA(A1, 0, a0v, a1v);
        loadW(w1_slot, 0, wv);
        storeTile(0, a0v, a1v, wv);
    }
    __syncthreads();

    const int mbase = wm * 32;
    const int nbase = wn * 64;
    const int fr = lane >> 2;
    const int fc = lane & 3;

    for (int it = 0; it < total; it++) {
        int buf = it & 1;
        uint2 pa0, pa1;
        uint4 pwv;
        bool more = (it + 1) < total;
        if (more) {
            int nit = it + 1;
            const __half* A = (DUAL && nit >= itersPerPass) ? A2 : A1;
            int slot = (DUAL && nit >= itersPerPass) ? w2_slot : w1_slot;
            int kk = (nit & (itersPerPass - 1)) * BK;
            loadA(A, kk, pa0, pa1);
            loadW(slot, kk, pwv);
        }

        uint32_t af[2][4];
#pragma unroll
        for (int mt = 0; mt < 2; mt++) {
            int r = mbase + mt * 16 + fr;
            af[mt][0] = As[buf][r][fc];
            af[mt][1] = As[buf][r + 8][fc];
            af[mt][2] = As[buf][r][fc + 4];
            af[mt][3] = As[buf][r + 8][fc + 4];
        }
        uint32_t bf[8][2];
#pragma unroll
        for (int nt = 0; nt < 8; nt++) {
            int n = nbase + nt * 8 + fr;
            bf[nt][0] = Ws[buf][fc][n];
            bf[nt][1] = Ws[buf][fc + 4][n];
        }
#pragma unroll
        for (int mt = 0; mt < 2; mt++)
#pragma unroll
            for (int nt = 0; nt < 8; nt++)
                mma_f16(acc[mt][nt], af[mt][0], af[mt][1], af[mt][2], af[mt][3],
                        bf[nt][0], bf[nt][1]);

        if (more) storeTile(buf ^ 1, pa0, pa1, pwv);
        __syncthreads();
    }

    // epilogue: write half2
#pragma unroll
    for (int mt = 0; mt < 2; mt++) {
#pragma unroll
        for (int nt = 0; nt < 8; nt++) {
            int gn = n0 + nbase + nt * 8 + 2 * fc;
            float b0 = BIAS ? bias[gn] : 0.f;
            float b1 = BIAS ? bias[gn + 1] : 0.f;
            int gm0 = m0 + mbase + mt * 16 + fr;
            int gm1 = gm0 + 8;
            float2 v0, v1;
            v0.x = acc[mt][nt][0] + b0; v0.y = acc[mt][nt][1] + b1;
            v1.x = acc[mt][nt][2] + b0; v1.y = acc[mt][nt][3] + b1;
            if (RELU) {
                v0.x = fmaxf(v0.x, 0.f); v0.y = fmaxf(v0.y, 0.f);
                v1.x = fmaxf(v1.x, 0.f); v1.y = fmaxf(v1.y, 0.f);
            }
            if (gm0 < N_NODES)
                *(uint32_t*)(C + (size_t)gm0 * 256 + gn) = packh2(v0.x, v0.y);
            if (gm1 < N_NODES)
                *(uint32_t*)(C + (size_t)gm1 * 256 + gn) = packh2(v1.x, v1.y);
        }
    }
}

template <bool DUAL, bool RELU, bool BIAS>
__global__ __launch_bounds__(256, 2)
void gemm_kernel(int a1_sel, int w1_slot, int a2_sel, int w2_slot,
                 const float* __restrict__ biasp, int c_sel) {
    gemm_body<DUAL, RELU, BIAS>(selbufh(a1_sel), w1_slot,
                                DUAL ? selbufh(a2_sel) : nullptr, w2_slot,
                                biasp, selbufh(c_sel),
                                blockIdx.y * BM, blockIdx.x * BN);
}

// merged edge precompute: blockIdx.x 0,1 -> bufA = h2@Wm1_top (slot 4, no bias)
//                         blockIdx.x 2,3 -> bufB = h2@Wm1_bot (slot 5) + bm1
__global__ __launch_bounds__(256, 2)
void gemm_pre_kernel(const float* __restrict__ bm1) {
    int half = blockIdx.x >> 1;
    int n0 = (blockIdx.x & 1) * BN;
    __half* C = half ? g_bufB : g_bufA;
    if (half)
        gemm_body<false, false, true>(g_bufC, 5, nullptr, 0, bm1, C,
                                      blockIdx.y * BM, n0);
    else
        gemm_body<false, false, false>(g_bufC, 4, nullptr, 0, nullptr, C,
                                       blockIdx.y * BM, n0);
}

// ---------------- edge MLP, CSR order: one warp per DST node ----------------
__global__ void edge_kernel_csr(const float* __restrict__ Wm2,
                                const float* __restrict__ bm2,
                                float* __restrict__ out) {
    __shared__ __align__(16) float w0[256];
    __shared__ __align__(16) float w1[256];
    for (int i = threadIdx.x; i < 256; i += blockDim.x) {
        w0[i] = Wm2[i * 2 + 0];
        w1[i] = Wm2[i * 2 + 1];
    }
    __syncthreads();

    int gtid = blockIdx.x * blockDim.x + threadIdx.x;
    int node = gtid >> 5;
    int lane = gtid & 31;
    if (node >= N_NODES) return;

    int beg = g_rowptr[node], end = g_rowptr[node + 1];
    if (beg == end) return;

    float b[8];
    {
        uint4 bv = *(const uint4*)(g_bufB + (size_t)node * D + lane * 8);
        const __half2* h = (const __half2*)&bv;
#pragma unroll
        for (int j = 0; j < 4; j++) {
            float2 f = __half22float2(h[j]);
            b[2 * j] = f.x;
            b[2 * j + 1] = f.y;
        }
    }
    float wa[8], wb[8];
    {
        const float4* w0f = (const float4*)w0;
        const float4* w1f = (const float4*)w1;
        float4 t0 = w0f[lane * 2], t1 = w0f[lane * 2 + 1];
        wa[0] = t0.x; wa[1] = t0.y; wa[2] = t0.z; wa[3] = t0.w;
        wa[4] = t1.x; wa[5] = t1.y; wa[6] = t1.z; wa[7] = t1.w;
        float4 s0 = w1f[lane * 2], s1 = w1f[lane * 2 + 1];
        wb[0] = s0.x; wb[1] = s0.y; wb[2] = s0.z; wb[3] = s0.w;
        wb[4] = s1.x; wb[5] = s1.y; wb[6] = s1.z; wb[7] = s1.w;
    }

    float bias0 = bm2[0], bias1 = bm2[1];

    for (int p = beg; p < end; p++) {
        int2 se = g_edge[p];
        int s = se.x;
        int eid = se.y;
        uint4 av = *(const uint4*)(g_bufA + (size_t)s * D + lane * 8);
        const __half2* h = (const __half2*)&av;

        float acc0 = 0.f, acc1 = 0.f;
#pragma unroll
        for (int j = 0; j < 4; j++) {
            float2 f = __half22float2(h[j]);
            float v0 = fmaxf(f.x + b[2 * j], 0.f);
            float v1 = fmaxf(f.y + b[2 * j + 1], 0.f);
            acc0 = fmaf(v0, wa[2 * j], acc0);
            acc0 = fmaf(v1, wa[2 * j + 1], acc0);
            acc1 = fmaf(v0, wb[2 * j], acc1);
            acc1 = fmaf(v1, wb[2 * j + 1], acc1);
        }

#pragma unroll
        for (int o = 16; o > 0; o >>= 1) {
            acc0 += __shfl_xor_sync(0xFFFFFFFFu, acc0, o);
            acc1 += __shfl_xor_sync(0xFFFFFFFFu, acc1, o);
        }
        if (lane == 0) {
            float2 r;
            r.x = acc0 + bias0;
            r.y = acc1 + bias1;
            *(float2*)(out + (size_t)eid * 2) = r;
        }
    }
}

// ---------------- launch ----------------
extern "C" void kernel_launch(void* const* d_in, const int* in_sizes, int n_in,
                              void* d_out, int out_size) {
    const float* x   = (const float*)d_in[0];
    const void*  ei  = d_in[1];
    const float* W1l = (const float*)d_in[2];
    const float* b1l = (const float*)d_in[3];
    const float* W1r = (const float*)d_in[4];
    const float* W2l = (const float*)d_in[5];
    const float* b2l = (const float*)d_in[6];
    const float* W2r = (const float*)d_in[7];
    const float* Wm1 = (const float*)d_in[8];
    const float* bm1 = (const float*)d_in[9];
    const float* Wm2 = (const float*)d_in[10];
    const float* bm2 = (const float*)d_in[11];
    float* out = (float*)d_out;

    // dtype detect + zero degrees; x/W -> fp16; count
    detect_zero_kernel<<<(N_NODES + 255) / 256, 256>>>((const int*)ei);
    convert_x_kernel<<<(N_NODES * D / 8 + 255) / 256, 256>>>(x);
    convert_w_kernel<<<dim3(128, 6), 256>>>(W1l, W1r, W2l, W2r, Wm1);
    count_kernel<<<(N_EDGES + 255) / 256, 256>>>(ei);

    // parallel CSR scan (3 phases) + fill
    block_reduce_kernel<<<SCAN_BLOCKS, 1024>>>();
    scan_bsum_kernel<<<1, 64>>>();
    block_scan_kernel<<<SCAN_BLOCKS, 1024>>>();
    fill_kernel<<<(N_EDGES + 255) / 256, 256>>>(ei);

    dim3 ggrid(2, GEMM_MBLKS);
    dim3 pgrid(4, GEMM_MBLKS);
    int aggBlocks = (N_NODES * 32 + 255) / 256;

    // layer 1: agg(x16) -> bufA ; h1 = relu(agg@W1l + x16@W1r + b1l) -> bufB
    aggregate16_kernel<<<aggBlocks, 256>>>(3, 0);
    gemm_kernel<true, true, true><<<ggrid, 256>>>(0, 0, 3, 1, b1l, 1);

    // layer 2: agg(h1) -> bufA ; h2 = relu(agg@W2l + h1@W2r + b2l) -> bufC
    aggregate16_kernel<<<aggBlocks, 256>>>(1, 0);
    gemm_kernel<true, true, true><<<ggrid, 256>>>(0, 2, 1, 3, b2l, 2);

    // merged edge precompute: bufA = h2@Wm1_top ; bufB = h2@Wm1_bot + bm1
    gemm_pre_kernel<<<pgrid, 256>>>(bm1);

    // edge MLP in CSR (dst-grouped) order
    edge_kernel_csr<<<aggBlocks, 256>>>(Wm2, bm2, out);
}

// round 17
// speedup vs baseline: 2.6170x; 1.0392x over previous
#include <cuda_runtime.h>
#include <cuda_fp16.h>
#include <cstdint>

#define N_NODES 50000
#define N_EDGES 800000
#define D 256

#define BM 128
#define BN 128
#define BK 16
#define GEMM_MBLKS 391            // ceil(50000/128)
#define SCAN_BLOCKS 49            // ceil(50000/1024)
#define WSLOT 32768               // half2 per weight panel (256*256/2)

#define XCONV_BLKS 6250           // 50000*256/8/256
#define WCONV_BLKS 768            // 6 slots * 128 kp-blocks
#define COUNT_BLKS 3125           // 800000/256

// ---------------- scratch (device globals; no allocations) ----------------
__device__ int      g_is64;
__device__ int      g_deg[N_NODES];
__device__ int      g_bsum[SCAN_BLOCKS];
__device__ int      g_rowptr[N_NODES + 1];
__device__ int      g_cursor[N_NODES];
__device__ int2     g_edge[N_EDGES];        // (src, eid) packed, CSR order
__device__ uint32_t g_w16[6 * WSLOT];       // fp16 weights, k-pair interleaved
__device__ __half   g_x16[N_NODES * D];     // fp16 copy of x
__device__ __half   g_bufA[N_NODES * D];    // agg scratch, later A_pre
__device__ __half   g_bufB[N_NODES * D];    // h1, later B_pre
__device__ __half   g_bufC[N_NODES * D];    // h2

__device__ __forceinline__ __half* selbufh(int s) {
    if (s == 0) return g_bufA;
    if (s == 1) return g_bufB;
    if (s == 2) return g_bufC;
    return g_x16;   // 3
}

__device__ __forceinline__ uint32_t packh2(float a, float b) {
    __half2 h = __floats2half2_rn(a, b);
    return *(uint32_t*)&h;
}

__device__ __forceinline__ int dec_dst(const void* ei, int e) {
    return g_is64 ? (int)((const long long*)ei)[N_EDGES + e]
                  : ((const int*)ei)[N_EDGES + e];
}
__device__ __forceinline__ int dec_src(const void* ei, int e) {
    return g_is64 ? (int)((const long long*)ei)[e]
                  : ((const int*)ei)[e];
}

// ---------------- detect dtype + zero degrees (fused) ----------------
__global__ void detect_zero_kernel(const int* __restrict__ ei32) {
    int i = blockIdx.x * blockDim.x + threadIdx.x;
    if (i < N_NODES) g_deg[i] = 0;
    if (i == 0) {
        int allzero = 1;
        for (int j = 1; j < 256; j += 2) {
            if (ei32[j] != 0) { allzero = 0; break; }
        }
        g_is64 = allzero;
    }
}

// ---------------- fused prologue: x->fp16 | W->fp16 | degree count -------
__global__ void prologue_kernel(const float* __restrict__ x,
                                const float* __restrict__ W1l,
                                const float* __restrict__ W1r,
                                const float* __restrict__ W2l,
                                const float* __restrict__ W2r,
                                const float* __restrict__ Wm1,
                                const void* __restrict__ ei) {
    int b = blockIdx.x;
    if (b < XCONV_BLKS) {
        // x -> fp16, 8 floats per thread
        int i = b * 256 + threadIdx.x;
        const float4* p = (const float4*)(x + (size_t)i * 8);
        float4 a = p[0], c = p[1];
        uint4 o;
        o.x = packh2(a.x, a.y); o.y = packh2(a.z, a.w);
        o.z = packh2(c.x, c.y); o.w = packh2(c.z, c.w);
        *(uint4*)(g_x16 + (size_t)i * 8) = o;
    } else if (b < XCONV_BLKS + WCONV_BLKS) {
        // weights -> fp16 k-pair interleaved:
        // g_w16[slot*WSLOT + kp*256 + n] = half2(W[2kp][n], W[2kp+1][n])
        int wb = b - XCONV_BLKS;
        int slot = wb >> 7;          // /128
        int kp = wb & 127;
        const float* W;
        if (slot == 0) W = W1l;
        else if (slot == 1) W = W1r;
        else if (slot == 2) W = W2l;
        else if (slot == 3) W = W2r;
        else if (slot == 4) W = Wm1;
        else W = Wm1 + 256 * 256;
        int n = threadIdx.x;
        float lo = W[(size_t)(2 * kp) * 256 + n];
        float hi = W[(size_t)(2 * kp + 1) * 256 + n];
        g_w16[slot * WSLOT + kp * 256 + n] = packh2(lo, hi);
    } else {
        // degree count
        int e = (b - XCONV_BLKS - WCONV_BLKS) * 256 + threadIdx.x;
        if (e < N_EDGES) atomicAdd(&g_deg[dec_dst(ei, e)], 1);
    }
}

// ---------------- parallel CSR prefix scan (3 phases) ----------------
__global__ void block_reduce_kernel() {
    __shared__ int sh[32];
    int i = blockIdx.x * 1024 + threadIdx.x;
    int v = (i < N_NODES) ? g_deg[i] : 0;
#pragma unroll
    for (int o = 16; o > 0; o >>= 1) v += __shfl_xor_sync(0xFFFFFFFFu, v, o);
    if ((threadIdx.x & 31) == 0) sh[threadIdx.x >> 5] = v;
    __syncthreads();
    if (threadIdx.x < 32) {
        int w = sh[threadIdx.x];
#pragma unroll
        for (int o = 16; o > 0; o >>= 1) w += __shfl_xor_sync(0xFFFFFFFFu, w, o);
        if (threadIdx.x == 0) g_bsum[blockIdx.x] = w;
    }
}

__global__ void scan_bsum_kernel() {
    __shared__ int sh[64];
    int t = threadIdx.x;
    int v = (t < SCAN_BLOCKS) ? g_bsum[t] : 0;
    sh[t] = v;
    __syncthreads();
    for (int o = 1; o < 64; o <<= 1) {
        int u = (t >= o) ? sh[t - o] : 0;
        __syncthreads();
        sh[t] += u;
        __syncthreads();
    }
    if (t < SCAN_BLOCKS) g_bsum[t] = sh[t] - v;   // exclusive prefix
}

__global__ void block_scan_kernel() {
    __shared__ int sh[1024];
    int t = threadIdx.x;
    int i = blockIdx.x * 1024 + t;
    int v = (i < N_NODES) ? g_deg[i] : 0;
    sh[t] = v;
    __syncthreads();
    for (int o = 1; o < 1024; o <<= 1) {
        int u = (t >= o) ? sh[t - o] : 0;
        __syncthreads();
        sh[t] += u;
        __syncthreads();
    }
    if (i < N_NODES) {
        int run = g_bsum[blockIdx.x] + sh[t] - v;   // exclusive
        g_rowptr[i] = run;
        g_cursor[i] = run;
    }
    if (blockIdx.x == 0 && t == 0) g_rowptr[N_NODES] = N_EDGES;
}

__global__ void fill_kernel(const void* __restrict__ ei) {
    int e = blockIdx.x * blockDim.x + threadIdx.x;
    if (e < N_EDGES) {
        int d = dec_dst(ei, e);
        int s = dec_src(ei, e);
        int pos = atomicAdd(&g_cursor[d], 1);
        g_edge[pos] = make_int2(s, e);
    }
}

// ---------------- mean aggregation (fp16, fp32 accum, 4-edge unroll) ------
__global__ void aggregate16_kernel(int in_sel, int out_sel) {
    const __half* in = selbufh(in_sel);
    __half* out = selbufh(out_sel);
    int gtid = blockIdx.x * blockDim.x + threadIdx.x;
    int node = gtid >> 5;
    int lane = gtid & 31;
    if (node >= N_NODES) return;
    int beg = g_rowptr[node], end = g_rowptr[node + 1];
    float acc[8] = {0.f, 0.f, 0.f, 0.f, 0.f, 0.f, 0.f, 0.f};
    int off = lane * 8;
    int p = beg;
    for (; p + 4 <= end; p += 4) {
        int s0 = g_edge[p].x, s1 = g_edge[p + 1].x;
        int s2 = g_edge[p + 2].x, s3 = g_edge[p + 3].x;
        uint4 v0 = *(const uint4*)(in + (size_t)s0 * D + off);
        uint4 v1 = *(const uint4*)(in + (size_t)s1 * D + off);
        uint4 v2 = *(const uint4*)(in + (size_t)s2 * D + off);
        uint4 v3 = *(const uint4*)(in + (size_t)s3 * D + off);
        const __half2* h0 = (const __half2*)&v0;
        const __half2* h1 = (const __half2*)&v1;
        const __half2* h2 = (const __half2*)&v2;
        const __half2* h3 = (const __half2*)&v3;
#pragma unroll
        for (int j = 0; j < 4; j++) {
            float2 f0 = __half22float2(h0[j]);
            float2 f1 = __half22float2(h1[j]);
            float2 f2 = __half22float2(h2[j]);
            float2 f3 = __half22float2(h3[j]);
            acc[2 * j]     += f0.x; acc[2 * j + 1] += f0.y;
            acc[2 * j]     += f1.x; acc[2 * j + 1] += f1.y;
            acc[2 * j]     += f2.x; acc[2 * j + 1] += f2.y;
            acc[2 * j]     += f3.x; acc[2 * j + 1] += f3.y;
        }
    }
    for (; p < end; p++) {
        int s = g_edge[p].x;
        uint4 v = *(const uint4*)(in + (size_t)s * D + off);
        const __half2* h = (const __half2*)&v;
#pragma unroll
        for (int j = 0; j < 4; j++) {
            float2 f = __half22float2(h[j]);
            acc[2 * j] += f.x;
            acc[2 * j + 1] += f.y;
        }
    }
    float inv = 1.f / fmaxf((float)(end - beg), 1.f);
    uint4 o;
    o.x = packh2(acc[0] * inv, acc[1] * inv);
    o.y = packh2(acc[2] * inv, acc[3] * inv);
    o.z = packh2(acc[4] * inv, acc[5] * inv);
    o.w = packh2(acc[6] * inv, acc[7] * inv);
    *(uint4*)(out + (size_t)node * D + off) = o;
}

// ---------------- fp16 tensor-core GEMM ----------------
__device__ __forceinline__ void mma_f16(float* c, uint32_t a0, uint32_t a1,
                                        uint32_t a2, uint32_t a3,
                                        uint32_t b0, uint32_t b1) {
    asm volatile(
        "mma.sync.aligned.m16n8k16.row.col.f32.f16.f16.f32 "
        "{%0,%1,%2,%3}, {%4,%5,%6,%7}, {%8,%9}, {%0,%1,%2,%3};"
        : "+f"(c[0]), "+f"(c[1]), "+f"(c[2]), "+f"(c[3])
        : "r"(a0), "r"(a1), "r"(a2), "r"(a3), "r"(b0), "r"(b1));
}

template <bool DUAL, bool RELU, bool BIAS>
__device__ __forceinline__ void gemm_body(
    const __half* __restrict__ A1, int w1_slot,
    const __half* __restrict__ A2, int w2_slot,
    const float* __restrict__ bias, __half* __restrict__ C,
    int m0, int n0) {
    __shared__ uint32_t As[2][BM][12];        // 8 half2 cols + 4 pad
    __shared__ uint32_t Ws[2][8][BN + 8];     // 8 k-pair rows, stride 136

    const int tid = threadIdx.x;
    const int lane = tid & 31;
    const int warp = tid >> 5;
    const int wm = warp & 3;
    const int wn = warp >> 2;

    const int itersPerPass = 256 / BK;           // 16
    const int total = DUAL ? 2 * itersPerPass : itersPerPass;

    float acc[2][8][4];
#pragma unroll
    for (int i = 0; i < 2; i++)
#pragma unroll
        for (int j = 0; j < 8; j++)
#pragma unroll
            for (int r = 0; r < 4; r++) acc[i][j][r] = 0.f;

    const int ar0 = tid >> 2, ac0 = (tid & 3) * 4, ah0 = (tid & 3) * 2;
    const int ar1 = (tid + 256) >> 2;
    const int wi = tid >> 5, wn4 = (tid & 31) * 4;

    auto loadA = [&](const __half* A, int kk, uint2& v0, uint2& v1) {
        int gm0 = m0 + ar0, gm1 = m0 + ar1;
        v0 = (gm0 < N_NODES) ? *(const uint2*)(A + (size_t)gm0 * 256 + kk + ac0)
                             : make_uint2(0u, 0u);
        v1 = (gm1 < N_NODES) ? *(const uint2*)(A + (size_t)gm1 * 256 + kk + ac0)
                             : make_uint2(0u, 0u);
    };
    auto loadW = [&](int slot, int kk, uint4& v) {
        const uint32_t* Wp = g_w16 + slot * WSLOT;
        v = *(const uint4*)(Wp + (kk / 2 + wi) * 256 + n0 + wn4);
    };
    auto storeTile = [&](int buf, const uint2& a0v, const uint2& a1v,
                         const uint4& wv) {
        *(uint2*)&As[buf][ar0][ah0] = a0v;
        *(uint2*)&As[buf][ar1][ah0] = a1v;
        *(uint4*)&Ws[buf][wi][wn4] = wv;
    };

    {
        uint2 a0v, a1v;
        uint4 wv;
        loadA(A1, 0, a0v, a1v);
        loadW(w1_slot, 0, wv);
        storeTile(0, a0v, a1v, wv);
    }
    __syncthreads();

    const int mbase = wm * 32;
    const int nbase = wn * 64;
    const int fr = lane >> 2;
    const int fc = lane & 3;

    for (int it = 0; it < total; it++) {
        int buf = it & 1;
        uint2 pa0, pa1;
        uint4 pwv;
        bool more = (it + 1) < total;
        if (more) {
            int nit = it + 1;
            const __half* A = (DUAL && nit >= itersPerPass) ? A2 : A1;
            int slot = (DUAL && nit >= itersPerPass) ? w2_slot : w1_slot;
            int kk = (nit & (itersPerPass - 1)) * BK;
            loadA(A, kk, pa0, pa1);
            loadW(slot, kk, pwv);
        }

        uint32_t af[2][4];
#pragma unroll
        for (int mt = 0; mt < 2; mt++) {
            int r = mbase + mt * 16 + fr;
            af[mt][0] = As[buf][r][fc];
            af[mt][1] = As[buf][r + 8][fc];
            af[mt][2] = As[buf][r][fc + 4];
            af[mt][3] = As[buf][r + 8][fc + 4];
        }
        uint32_t bf[8][2];
#pragma unroll
        for (int nt = 0; nt < 8; nt++) {
            int n = nbase + nt * 8 + fr;
            bf[nt][0] = Ws[buf][fc][n];
            bf[nt][1] = Ws[buf][fc + 4][n];
        }
#pragma unroll
        for (int mt = 0; mt < 2; mt++)
#pragma unroll
            for (int nt = 0; nt < 8; nt++)
                mma_f16(acc[mt][nt], af[mt][0], af[mt][1], af[mt][2], af[mt][3],
                        bf[nt][0], bf[nt][1]);

        if (more) storeTile(buf ^ 1, pa0, pa1, pwv);
        __syncthreads();
    }

    // epilogue: write half2
#pragma unroll
    for (int mt = 0; mt < 2; mt++) {
#pragma unroll
        for (int nt = 0; nt < 8; nt++) {
            int gn = n0 + nbase + nt * 8 + 2 * fc;
            float b0 = BIAS ? bias[gn] : 0.f;
            float b1 = BIAS ? bias[gn + 1] : 0.f;
            int gm0 = m0 + mbase + mt * 16 + fr;
            int gm1 = gm0 + 8;
            float2 v0, v1;
            v0.x = acc[mt][nt][0] + b0; v0.y = acc[mt][nt][1] + b1;
            v1.x = acc[mt][nt][2] + b0; v1.y = acc[mt][nt][3] + b1;
            if (RELU) {
                v0.x = fmaxf(v0.x, 0.f); v0.y = fmaxf(v0.y, 0.f);
                v1.x = fmaxf(v1.x, 0.f); v1.y = fmaxf(v1.y, 0.f);
            }
            if (gm0 < N_NODES)
                *(uint32_t*)(C + (size_t)gm0 * 256 + gn) = packh2(v0.x, v0.y);
            if (gm1 < N_NODES)
                *(uint32_t*)(C + (size_t)gm1 * 256 + gn) = packh2(v1.x, v1.y);
        }
    }
}

template <bool DUAL, bool RELU, bool BIAS>
__global__ __launch_bounds__(256, 2)
void gemm_kernel(int a1_sel, int w1_slot, int a2_sel, int w2_slot,
                 const float* __restrict__ biasp, int c_sel) {
    gemm_body<DUAL, RELU, BIAS>(selbufh(a1_sel), w1_slot,
                                DUAL ? selbufh(a2_sel) : nullptr, w2_slot,
                                biasp, selbufh(c_sel),
                                blockIdx.y * BM, blockIdx.x * BN);
}

// merged edge precompute: blockIdx.x 0,1 -> bufA = h2@Wm1_top (slot 4, no bias)
//                         blockIdx.x 2,3 -> bufB = h2@Wm1_bot (slot 5) + bm1
__global__ __launch_bounds__(256, 2)
void gemm_pre_kernel(const float* __restrict__ bm1) {
    int half = blockIdx.x >> 1;
    int n0 = (blockIdx.x & 1) * BN;
    __half* C = half ? g_bufB : g_bufA;
    if (half)
        gemm_body<false, false, true>(g_bufC, 5, nullptr, 0, bm1, C,
                                      blockIdx.y * BM, n0);
    else
        gemm_body<false, false, false>(g_bufC, 4, nullptr, 0, nullptr, C,
                                       blockIdx.y * BM, n0);
}

// ---------------- edge MLP, CSR order, 2-edge unroll ----------------
__global__ void edge_kernel_csr(const float* __restrict__ Wm2,
                                const float* __restrict__ bm2,
                                float* __restrict__ out) {
    __shared__ __align__(16) float w0[256];
    __shared__ __align__(16) float w1[256];
    for (int i = threadIdx.x; i < 256; i += blockDim.x) {
        w0[i] = Wm2[i * 2 + 0];
        w1[i] = Wm2[i * 2 + 1];
    }
    __syncthreads();

    int gtid = blockIdx.x * blockDim.x + threadIdx.x;
    int node = gtid >> 5;
    int lane = gtid & 31;
    if (node >= N_NODES) return;

    int beg = g_rowptr[node], end = g_rowptr[node + 1];
    if (beg == end) return;

    int off = lane * 8;

    float b[8];
    {
        uint4 bv = *(const uint4*)(g_bufB + (size_t)node * D + off);
        const __half2* h = (const __half2*)&bv;
#pragma unroll
        for (int j = 0; j < 4; j++) {
            float2 f = __half22float2(h[j]);
            b[2 * j] = f.x;
            b[2 * j + 1] = f.y;
        }
    }
    float wa[8], wb[8];
    {
        const float4* w0f = (const float4*)w0;
        const float4* w1f = (const float4*)w1;
        float4 t0 = w0f[lane * 2], t1 = w0f[lane * 2 + 1];
        wa[0] = t0.x; wa[1] = t0.y; wa[2] = t0.z; wa[3] = t0.w;
        wa[4] = t1.x; wa[5] = t1.y; wa[6] = t1.z; wa[7] = t1.w;
        float4 s0 = w1f[lane * 2], s1 = w1f[lane * 2 + 1];
        wb[0] = s0.x; wb[1] = s0.y; wb[2] = s0.z; wb[3] = s0.w;
        wb[4] = s1.x; wb[5] = s1.y; wb[6] = s1.z; wb[7] = s1.w;
    }

    float bias0 = bm2[0], bias1 = bm2[1];

    int p = beg;
    for (; p + 2 <= end; p += 2) {
        int2 se0 = g_edge[p];
        int2 se1 = g_edge[p + 1];
        uint4 av0 = *(const uint4*)(g_bufA + (size_t)se0.x * D + off);
        uint4 av1 = *(const uint4*)(g_bufA + (size_t)se1.x * D + off);
        const __half2* h0 = (const __half2*)&av0;
        const __half2* h1 = (const __half2*)&av1;

        float a00 = 0.f, a01 = 0.f, a10 = 0.f, a11 = 0.f;
#pragma unroll
        for (int j = 0; j < 4; j++) {
            float2 f0 = __half22float2(h0[j]);
            float v0 = fmaxf(f0.x + b[2 * j], 0.f);
            float v1 = fmaxf(f0.y + b[2 * j + 1], 0.f);
            a00 = fmaf(v0, wa[2 * j], a00);
            a00 = fmaf(v1, wa[2 * j + 1], a00);
            a01 = fmaf(v0, wb[2 * j], a01);
            a01 = fmaf(v1, wb[2 * j + 1], a01);
            float2 f1 = __half22float2(h1[j]);
            float u0 = fmaxf(f1.x + b[2 * j], 0.f);
            float u1 = fmaxf(f1.y + b[2 * j + 1], 0.f);
            a10 = fmaf(u0, wa[2 * j], a10);
            a10 = fmaf(u1, wa[2 * j + 1], a10);
            a11 = fmaf(u0, wb[2 * j], a11);
            a11 = fmaf(u1, wb[2 * j + 1], a11);
        }

#pragma unroll
        for (int o = 16; o > 0; o >>= 1) {
            a00 += __shfl_xor_sync(0xFFFFFFFFu, a00, o);
            a01 += __shfl_xor_sync(0xFFFFFFFFu, a01, o);
            a10 += __shfl_xor_sync(0xFFFFFFFFu, a10, o);
            a11 += __shfl_xor_sync(0xFFFFFFFFu, a11, o);
        }
        if (lane == 0) {
            float2 r0, r1;
            r0.x = a00 + bias0; r0.y = a01 + bias1;
            r1.x = a10 + bias0; r1.y = a11 + bias1;
            *(float2*)(out + (size_t)se0.y * 2) = r0;
            *(float2*)(out + (size_t)se1.y * 2) = r1;
        }
    }
    for (; p < end; p++) {
        int2 se = g_edge[p];
        uint4 av = *(const uint4*)(g_bufA + (size_t)se.x * D + off);
        const __half2* h = (const __half2*)&av;
        float acc0 = 0.f, acc1 = 0.f;
#pragma unroll
        for (int j = 0; j < 4; j++) {
            float2 f = __half22float2(h[j]);
            float v0 = fmaxf(f.x + b[2 * j], 0.f);
            float v1 = fmaxf(f.y + b[2 * j + 1], 0.f);
            acc0 = fmaf(v0, wa[2 * j], acc0);
            acc0 = fmaf(v1, wa[2 * j + 1], acc0);
            acc1 = fmaf(v0, wb[2 * j], acc1);
            acc1 = fmaf(v1, wb[2 * j + 1], acc1);
        }
#pragma unroll
        for (int o = 16; o > 0; o >>= 1) {
            acc0 += __shfl_xor_sync(0xFFFFFFFFu, acc0, o);
            acc1 += __shfl_xor_sync(0xFFFFFFFFu, acc1, o);
        }
        if (lane == 0) {
            float2 r;
            r.x = acc0 + bias0;
            r.y = acc1 + bias1;
            *(float2*)(out + (size_t)se.y * 2) = r;
        }
    }
}

// ---------------- launch ----------------
extern "C" void kernel_launch(void* const* d_in, const int* in_sizes, int n_in,
                              void* d_out, int out_size) {
    const float* x   = (const float*)d_in[0];
    const void*  ei  = d_in[1];
    const float* W1l = (const float*)d_in[2];
    const float* b1l = (const float*)d_in[3];
    const float* W1r = (const float*)d_in[4];
    const float* W2l = (const float*)d_in[5];
    const float* b2l = (const float*)d_in[6];
    const float* W2r = (const float*)d_in[7];
    const float* Wm1 = (const float*)d_in[8];
    const float* bm1 = (const float*)d_in[9];
    const float* Wm2 = (const float*)d_in[10];
    const float* bm2 = (const float*)d_in[11];
    float* out = (float*)d_out;

    // dtype detect + zero degrees, then fused x/W convert + count
    detect_zero_kernel<<<(N_NODES + 255) / 256, 256>>>((const int*)ei);
    prologue_kernel<<<XCONV_BLKS + WCONV_BLKS + COUNT_BLKS, 256>>>(
        x, W1l, W1r, W2l, W2r, Wm1, ei);

    // parallel CSR scan (3 phases) + fill
    block_reduce_kernel<<<SCAN_BLOCKS, 1024>>>();
    scan_bsum_kernel<<<1, 64>>>();
    block_scan_kernel<<<SCAN_BLOCKS, 1024>>>();
    fill_kernel<<<(N_EDGES + 255) / 256, 256>>>(ei);

    dim3 ggrid(2, GEMM_MBLKS);
    dim3 pgrid(4, GEMM_MBLKS);
    int aggBlocks = (N_NODES * 32 + 255) / 256;

    // layer 1: agg(x16) -> bufA ; h1 = relu(agg@W1l + x16@W1r + b1l) -> bufB
    aggregate16_kernel<<<aggBlocks, 256>>>(3, 0);
    gemm_kernel<true, true, true><<<ggrid, 256>>>(0, 0, 3, 1, b1l, 1);

    // layer 2: agg(h1) -> bufA ; h2 = relu(agg@W2l + h1@W2r + b2l) -> bufC
    aggregate16_kernel<<<aggBlocks, 256>>>(1, 0);
    gemm_kernel<true, true, true><<<ggrid, 256>>>(0, 2, 1, 3, b2l, 2);

    // merged edge precompute: bufA = h2@Wm1_top ; bufB = h2@Wm1_bot + bm1
    gemm_pre_kernel<<<pgrid, 256>>>(bm1);

    // edge MLP in CSR (dst-grouped) order
    edge_kernel_csr<<<aggBlocks, 256>>>(Wm2, bm2, out);
}